// round 4
// baseline (speedup 1.0000x reference)
#include <cuda_runtime.h>
#include <cstdint>

#define NB   2
#define NT   2048
#define ND   1024
#define NHH  16
#define NHD  64
#define NM   (NB * NT)   // 4096 rows

// Scratch (device globals: allocation is forbidden)
__device__ float g_X[NM * ND];               // tf32-rounded input
__device__ float g_Q[NB * NHH * NT * NHD];   // [b,h,t,hd]  (tf32-rounded)
__device__ float g_K[NB * NHH * NT * NHD];
__device__ float g_V[NB * NHH * NT * NHD];
__device__ float g_C[NM * ND];               // ctx (tf32-rounded)
__device__ float g_WT[4 * ND * ND];          // transposed weights [n][k] (tf32-rounded)

// ---------------------------------------------------------------------------
// Helpers
// ---------------------------------------------------------------------------
__device__ __forceinline__ uint32_t smem_u32(const void* p) {
    uint32_t a;
    asm("{ .reg .u64 t; cvta.to.shared.u64 t, %1; cvt.u32.u64 %0, t; }"
        : "=r"(a) : "l"(p));
    return a;
}
__device__ __forceinline__ uint32_t f2tf32(float x) {
    uint32_t r; asm("cvt.rna.tf32.f32 %0, %1;" : "=r"(r) : "f"(x)); return r;
}
__device__ __forceinline__ void cpa16(uint32_t dst, const void* src) {
    asm volatile("cp.async.cg.shared.global [%0], [%1], 16;" :: "r"(dst), "l"(src));
}
#define CP_COMMIT() asm volatile("cp.async.commit_group;" ::: "memory")
#define CP_WAIT0()  asm volatile("cp.async.wait_group 0;" ::: "memory")

// mma.sync m16n8k8 row.col tf32: d += a * b
__device__ __forceinline__ void mma8(float* d, const uint32_t* a,
                                     uint32_t b0, uint32_t b1)
{
    asm volatile(
        "mma.sync.aligned.m16n8k8.row.col.f32.tf32.tf32.f32 "
        "{%0,%1,%2,%3}, {%4,%5,%6,%7}, {%8,%9}, {%0,%1,%2,%3};"
        : "+f"(d[0]), "+f"(d[1]), "+f"(d[2]), "+f"(d[3])
        : "r"(a[0]), "r"(a[1]), "r"(a[2]), "r"(a[3]), "r"(b0), "r"(b1));
}

// ---------------------------------------------------------------------------
// Pre-round x into g_X (tf32 rna)
// ---------------------------------------------------------------------------
__global__ void round_x(const float* __restrict__ src, float* __restrict__ dst)
{
    const int i = (blockIdx.x * 256 + threadIdx.x) << 2;
    float4 v = *(const float4*)(src + i);
    uint4 u;
    u.x = f2tf32(v.x); u.y = f2tf32(v.y);
    u.z = f2tf32(v.z); u.w = f2tf32(v.w);
    *(uint4*)(dst + i) = u;
}

// ---------------------------------------------------------------------------
// Fused weight transpose + tf32 round: WT[z][n][k] = tf32(W_z[k][n])
// ---------------------------------------------------------------------------
__global__ void transpose_w4(const float* __restrict__ W0,
                             const float* __restrict__ W1,
                             const float* __restrict__ W2,
                             const float* __restrict__ W3,
                             float* __restrict__ WT)
{
    const float* W = (blockIdx.z == 0) ? W0 : (blockIdx.z == 1) ? W1
                   : (blockIdx.z == 2) ? W2 : W3;
    float* dst = WT + (size_t)blockIdx.z * ND * ND;

    __shared__ float t[32][33];
    const int x = (blockIdx.x << 5) + threadIdx.x;
    const int y0 = (blockIdx.y << 5) + threadIdx.y;
#pragma unroll
    for (int i = 0; i < 32; i += 8)
        t[threadIdx.y + i][threadIdx.x] = W[(size_t)(y0 + i) * ND + x];
    __syncthreads();
    const int x2 = (blockIdx.y << 5) + threadIdx.x;
    const int y2 = (blockIdx.x << 5) + threadIdx.y;
#pragma unroll
    for (int i = 0; i < 32; i += 8)
        dst[(size_t)(y2 + i) * ND + x2] =
            __uint_as_float(f2tf32(t[threadIdx.x][threadIdx.y + i]));
}

// ---------------------------------------------------------------------------
// tf32 mma.sync GEMM with cp.async 2-stage pipeline.
// Out[4096x1024] = A @ W  (A, BT pre-rounded to tf32; BT is [n][k])
// 128x128 block, BK=32, 256 thr = 8 warps (4m x 2n), warp tile 32x64.
// MODE 0: scatter to per-head [b,h,t,hd], tf32-rounded.  MODE 1: +bias fp32.
// ---------------------------------------------------------------------------
#define GA_STR 36
template <int MODE>
__global__ void __launch_bounds__(256) gemm_mma(
    const float* __restrict__ A, const float* __restrict__ BT,
    float* __restrict__ Out, const float* __restrict__ bias)
{
    extern __shared__ float sm[];
    float* As = sm;             // [2][128*36]
    float* Bs = sm + 2 * 128 * GA_STR;
    const uint32_t sbase = smem_u32(sm);
    const uint32_t boff = 2 * 128 * GA_STR * 4;   // byte offset of Bs

    const int tid = threadIdx.x;
    const int lane = tid & 31;
    const int wid = tid >> 5;
    const int g = lane >> 2, t = lane & 3;
    const int wm = wid & 3;        // 0..3  (32 rows each)
    const int wn = wid >> 2;       // 0..1  (64 cols each)
    const int m0 = blockIdx.y << 7;
    const int n0 = blockIdx.x << 7;

    const float* Ab = A  + (size_t)m0 * ND;
    const float* Bb = BT + (size_t)n0 * ND;

    float acc[2][8][4];
#pragma unroll
    for (int mt = 0; mt < 2; ++mt)
#pragma unroll
        for (int nt = 0; nt < 8; ++nt)
#pragma unroll
            for (int e = 0; e < 4; ++e) acc[mt][nt][e] = 0.f;

    // issue chunk c into buffer buf
    auto issue = [&](int c, int buf) {
        const int k0 = c << 5;
        const uint32_t bb = (uint32_t)buf * (128 * GA_STR * 4);
#pragma unroll
        for (int u = 0; u < 4; ++u) {
            const int f = (u << 8) + tid;
            const int row = f >> 3, kc = (f & 7) << 2;
            const uint32_t doff = bb + (uint32_t)(row * GA_STR + kc) * 4;
            cpa16(sbase + doff,        Ab + (size_t)row * ND + k0 + kc);
            cpa16(sbase + boff + doff, Bb + (size_t)row * ND + k0 + kc);
        }
        CP_COMMIT();
    };

    issue(0, 0);

    for (int c = 0; c < 32; ++c) {
        CP_WAIT0();
        __syncthreads();
        if (c < 31) issue(c + 1, (c + 1) & 1);

        const float* Ac = As + (c & 1) * (128 * GA_STR);
        const float* Bc = Bs + (c & 1) * (128 * GA_STR);
#pragma unroll
        for (int ks = 0; ks < 4; ++ks) {
            const int kk = ks << 3;
            uint32_t af[2][4];
#pragma unroll
            for (int mt = 0; mt < 2; ++mt) {
                const int rb_ = (wm << 5) + (mt << 4);
                af[mt][0] = __float_as_uint(Ac[(rb_ + g    ) * GA_STR + kk + t]);
                af[mt][1] = __float_as_uint(Ac[(rb_ + g + 8) * GA_STR + kk + t]);
                af[mt][2] = __float_as_uint(Ac[(rb_ + g    ) * GA_STR + kk + t + 4]);
                af[mt][3] = __float_as_uint(Ac[(rb_ + g + 8) * GA_STR + kk + t + 4]);
            }
#pragma unroll
            for (int nt = 0; nt < 8; ++nt) {
                const int cb = (wn << 6) + (nt << 3) + g;
                const uint32_t b0 = __float_as_uint(Bc[cb * GA_STR + kk + t]);
                const uint32_t b1 = __float_as_uint(Bc[cb * GA_STR + kk + t + 4]);
                mma8(acc[0][nt], af[0], b0, b1);
                mma8(acc[1][nt], af[1], b0, b1);
            }
        }
        __syncthreads();
    }

    // epilogue
#pragma unroll
    for (int mt = 0; mt < 2; ++mt) {
#pragma unroll
        for (int nt = 0; nt < 8; ++nt) {
            const int r0 = m0 + (wm << 5) + (mt << 4) + g;
            const int cc = n0 + (wn << 6) + (nt << 3) + (t << 1);
#pragma unroll
            for (int h = 0; h < 2; ++h) {
                const int m = r0 + (h << 3);
                float v0 = acc[mt][nt][h * 2 + 0];
                float v1 = acc[mt][nt][h * 2 + 1];
                if (MODE == 0) {
                    const int bb = m >> 11, tt = m & (NT - 1);
                    const int hh = cc >> 6, d = cc & 63;
                    float* o = Out + (((((size_t)bb * NHH + hh) * NT + tt) << 6) + d);
                    o[0] = __uint_as_float(f2tf32(v0));
                    o[1] = __uint_as_float(f2tf32(v1));
                } else {
                    float* o = Out + (size_t)m * ND + cc;
                    o[0] = v0 + bias[cc];
                    o[1] = v1 + bias[cc + 1];
                }
            }
        }
    }
}

// ---------------------------------------------------------------------------
// Causal flash attention, tf32 mma.sync, q-tile 128, cp.async double-buffered
// K/V tiles of 64. 256 threads = 8 warps, each warp owns 16 q rows.
// ---------------------------------------------------------------------------
#define KS_STR 68
#define VS_STR 72
__global__ void __launch_bounds__(256) attn_mma(
    const uint8_t* __restrict__ kpm, float* __restrict__ Cctx)
{
    extern __shared__ float sm[];
    float* Ksm = sm;                         // [2][64*68]
    float* Vsm = sm + 2 * 64 * KS_STR;       // [2][64*72]
    float* Msk = Vsm + 2 * 64 * VS_STR;      // [2][64]
    const uint32_t kbase = smem_u32(Ksm);
    const uint32_t vbase = smem_u32(Vsm);

    const int tid  = threadIdx.x;
    const int lane = tid & 31;
    const int w    = tid >> 5;               // warp 0..7, rows w*16..w*16+15
    const int g = lane >> 2, t = lane & 3;
    const int qi = blockIdx.x;
    const int bh = blockIdx.y;
    const int bb = bh >> 4, hh = bh & 15;
    const int q0 = qi << 7;

    const float* Qg = g_Q + ((size_t)bh * NT << 6);
    const float* Kg = g_K + ((size_t)bh * NT << 6);
    const float* Vg = g_V + ((size_t)bh * NT << 6);

    // Q fragments straight from gmem (pre-rounded)
    uint32_t qf[8][4];
    const int qr0 = q0 + (w << 4) + g;
#pragma unroll
    for (int ks = 0; ks < 8; ++ks) {
        const int kk = ks << 3;
        qf[ks][0] = __float_as_uint(Qg[((size_t)qr0 << 6) + kk + t]);
        qf[ks][1] = __float_as_uint(Qg[((size_t)(qr0 + 8) << 6) + kk + t]);
        qf[ks][2] = __float_as_uint(Qg[((size_t)qr0 << 6) + kk + t + 4]);
        qf[ks][3] = __float_as_uint(Qg[((size_t)(qr0 + 8) << 6) + kk + t + 4]);
    }

    const int r0 = qr0, r1 = qr0 + 8;
    float m0 = -1e30f, m1 = -1e30f, l0 = 0.f, l1 = 0.f;
    float oacc[8][4];
#pragma unroll
    for (int dt = 0; dt < 8; ++dt)
#pragma unroll
        for (int e = 0; e < 4; ++e) oacc[dt][e] = 0.f;

    const int ktmax = 2 * qi + 1;

    auto issueKV = [&](int kt, int buf) {
        const int k0 = kt << 6;
        const uint32_t kb = (uint32_t)buf * (64 * KS_STR * 4);
        const uint32_t vb = (uint32_t)buf * (64 * VS_STR * 4);
#pragma unroll
        for (int u = 0; u < 4; ++u) {
            const int f = (u << 8) + tid;
            const int r = f >> 4, slot = f & 15;
            cpa16(kbase + kb + (uint32_t)(r * KS_STR + (slot << 2)) * 4,
                  Kg + (((size_t)(k0 + r)) << 6) + (slot << 2));
            cpa16(vbase + vb + (uint32_t)(r * VS_STR + (slot << 2)) * 4,
                  Vg + (((size_t)(k0 + r)) << 6) + (slot << 2));
        }
        CP_COMMIT();
        if (tid < 64)
            Msk[buf * 64 + tid] = kpm[bb * NT + k0 + tid] ? -1e30f : 0.f;
    };

    issueKV(0, 0);

    for (int kt = 0; kt <= ktmax; ++kt) {
        CP_WAIT0();
        __syncthreads();
        if (kt < ktmax) issueKV(kt + 1, (kt + 1) & 1);

        const int k0 = kt << 6;
        // warp-level skip: this warp's rows entirely below this k-tile?
        if (k0 <= q0 + (w << 4) + 15) {
            const float* Kc = Ksm + (kt & 1) * (64 * KS_STR);
            const float* Vc = Vsm + (kt & 1) * (64 * VS_STR);
            const float* Mc = Msk + (kt & 1) * 64;

            // ---- S = Q K^T ----
            float sacc[8][4];
#pragma unroll
            for (int nt = 0; nt < 8; ++nt)
#pragma unroll
                for (int e = 0; e < 4; ++e) sacc[nt][e] = 0.f;

#pragma unroll
            for (int ks = 0; ks < 8; ++ks) {
                const int kk = ks << 3;
#pragma unroll
                for (int nt = 0; nt < 8; ++nt) {
                    const int kr = (nt << 3) + g;
                    const uint32_t b0 = __float_as_uint(Kc[kr * KS_STR + kk + t]);
                    const uint32_t b1 = __float_as_uint(Kc[kr * KS_STR + kk + t + 4]);
                    mma8(sacc[nt], qf[ks], b0, b1);
                }
            }

            // ---- scale + masks ----
            const bool diag = (k0 + 63 >= q0 + (w << 4));
            float mx0 = -1e30f, mx1 = -1e30f;
#pragma unroll
            for (int nt = 0; nt < 8; ++nt) {
                const int cl = (nt << 3) + (t << 1);
                const int kv0 = k0 + cl, kv1 = kv0 + 1;
                const float pm0 = Mc[cl], pm1 = Mc[cl + 1];
                float s0 = sacc[nt][0] * 0.125f + pm0;
                float s1 = sacc[nt][1] * 0.125f + pm1;
                float s2 = sacc[nt][2] * 0.125f + pm0;
                float s3 = sacc[nt][3] * 0.125f + pm1;
                if (diag) {
                    if (kv0 > r0) s0 = -1e30f;
                    if (kv1 > r0) s1 = -1e30f;
                    if (kv0 > r1) s2 = -1e30f;
                    if (kv1 > r1) s3 = -1e30f;
                }
                sacc[nt][0] = s0; sacc[nt][1] = s1;
                sacc[nt][2] = s2; sacc[nt][3] = s3;
                mx0 = fmaxf(mx0, fmaxf(s0, s1));
                mx1 = fmaxf(mx1, fmaxf(s2, s3));
            }
            mx0 = fmaxf(mx0, __shfl_xor_sync(0xffffffffu, mx0, 1));
            mx0 = fmaxf(mx0, __shfl_xor_sync(0xffffffffu, mx0, 2));
            mx1 = fmaxf(mx1, __shfl_xor_sync(0xffffffffu, mx1, 1));
            mx1 = fmaxf(mx1, __shfl_xor_sync(0xffffffffu, mx1, 2));

            const float nm0 = fmaxf(m0, mx0), nm1 = fmaxf(m1, mx1);
            const float cr0 = __expf(m0 - nm0), cr1 = __expf(m1 - nm1);
            m0 = nm0; m1 = nm1;

            float sum0 = 0.f, sum1 = 0.f;
#pragma unroll
            for (int nt = 0; nt < 8; ++nt) {
                float p0 = __expf(sacc[nt][0] - nm0);
                float p1 = __expf(sacc[nt][1] - nm0);
                float p2 = __expf(sacc[nt][2] - nm1);
                float p3 = __expf(sacc[nt][3] - nm1);
                sacc[nt][0] = p0; sacc[nt][1] = p1;
                sacc[nt][2] = p2; sacc[nt][3] = p3;
                sum0 += p0 + p1; sum1 += p2 + p3;
            }
            sum0 += __shfl_xor_sync(0xffffffffu, sum0, 1);
            sum0 += __shfl_xor_sync(0xffffffffu, sum0, 2);
            sum1 += __shfl_xor_sync(0xffffffffu, sum1, 1);
            sum1 += __shfl_xor_sync(0xffffffffu, sum1, 2);
            l0 = l0 * cr0 + sum0;
            l1 = l1 * cr1 + sum1;
#pragma unroll
            for (int dt = 0; dt < 8; ++dt) {
                oacc[dt][0] *= cr0; oacc[dt][1] *= cr0;
                oacc[dt][2] *= cr1; oacc[dt][3] *= cr1;
            }

            // ---- O += P V ----  (C-frag -> A-frag via quad shfls)
            const int srcA = (lane & ~3) | (t >> 1);
            const int srcB = srcA + 2;
            const bool odd = (t & 1);
#pragma unroll
            for (int kk = 0; kk < 8; ++kk) {
                const float pA0 = __shfl_sync(0xffffffffu, sacc[kk][0], srcA);
                const float pA1 = __shfl_sync(0xffffffffu, sacc[kk][1], srcA);
                const float pB0 = __shfl_sync(0xffffffffu, sacc[kk][0], srcB);
                const float pB1 = __shfl_sync(0xffffffffu, sacc[kk][1], srcB);
                const float pC0 = __shfl_sync(0xffffffffu, sacc[kk][2], srcA);
                const float pC1 = __shfl_sync(0xffffffffu, sacc[kk][3], srcA);
                const float pD0 = __shfl_sync(0xffffffffu, sacc[kk][2], srcB);
                const float pD1 = __shfl_sync(0xffffffffu, sacc[kk][3], srcB);
                uint32_t a[4];
                a[0] = f2tf32(odd ? pA1 : pA0);
                a[1] = f2tf32(odd ? pC1 : pC0);
                a[2] = f2tf32(odd ? pB1 : pB0);
                a[3] = f2tf32(odd ? pD1 : pD0);
#pragma unroll
                for (int dt = 0; dt < 8; ++dt) {
                    const int dc = (dt << 3) + g;
                    const uint32_t b0 = __float_as_uint(Vc[((kk << 3) + t    ) * VS_STR + dc]);
                    const uint32_t b1 = __float_as_uint(Vc[((kk << 3) + t + 4) * VS_STR + dc]);
                    mma8(oacc[dt], a, b0, b1);
                }
            }
        }
        __syncthreads();
    }

    // ---- normalize + write ctx [b*T+t, h*64+d], tf32-rounded ----
    const float i0 = 1.f / l0, i1 = 1.f / l1;
    const int mrow0 = (bb << 11) + q0 + (w << 4) + g;
#pragma unroll
    for (int dt = 0; dt < 8; ++dt) {
        const int dc = (hh << 6) + (dt << 3) + (t << 1);
        float* o0 = Cctx + (size_t)mrow0 * ND + dc;
        float* o1 = Cctx + (size_t)(mrow0 + 8) * ND + dc;
        o0[0] = __uint_as_float(f2tf32(oacc[dt][0] * i0));
        o0[1] = __uint_as_float(f2tf32(oacc[dt][1] * i0));
        o1[0] = __uint_as_float(f2tf32(oacc[dt][2] * i1));
        o1[1] = __uint_as_float(f2tf32(oacc[dt][3] * i1));
    }
}

// ---------------------------------------------------------------------------
extern "C" void kernel_launch(void* const* d_in, const int* in_sizes, int n_in,
                              void* d_out, int out_size)
{
    (void)in_sizes; (void)n_in; (void)out_size;
    const float*   x   = (const float*)d_in[0];
    const float*   Wq  = (const float*)d_in[1];
    const float*   Wk  = (const float*)d_in[2];
    const float*   Wv  = (const float*)d_in[3];
    const float*   Wo  = (const float*)d_in[4];
    const float*   bo  = (const float*)d_in[5];
    const uint8_t* kpm = (const uint8_t*)d_in[6];
    float* out = (float*)d_out;

    float *Xp, *Qp, *Kp, *Vp, *Cp, *WTp;
    cudaGetSymbolAddress((void**)&Xp, g_X);
    cudaGetSymbolAddress((void**)&Qp, g_Q);
    cudaGetSymbolAddress((void**)&Kp, g_K);
    cudaGetSymbolAddress((void**)&Vp, g_V);
    cudaGetSymbolAddress((void**)&Cp, g_C);
    cudaGetSymbolAddress((void**)&WTp, g_WT);

    round_x<<<(NM * ND) / (256 * 4), 256>>>(x, Xp);
    transpose_w4<<<dim3(32, 32, 4), dim3(32, 8)>>>(Wq, Wk, Wv, Wo, WTp);

    const int gsmem = 2 * 2 * 128 * GA_STR * (int)sizeof(float);  // 73728
    cudaFuncSetAttribute(gemm_mma<0>, cudaFuncAttributeMaxDynamicSharedMemorySize, gsmem);
    cudaFuncSetAttribute(gemm_mma<1>, cudaFuncAttributeMaxDynamicSharedMemorySize, gsmem);

    const dim3 gg(ND / 128, NM / 128);   // (8, 32)
    gemm_mma<0><<<gg, 256, gsmem>>>(Xp, WTp + 0 * ND * ND, Qp, nullptr);
    gemm_mma<0><<<gg, 256, gsmem>>>(Xp, WTp + 1 * ND * ND, Kp, nullptr);
    gemm_mma<0><<<gg, 256, gsmem>>>(Xp, WTp + 2 * ND * ND, Vp, nullptr);

    const int asmem = (2 * 64 * KS_STR + 2 * 64 * VS_STR + 2 * 64) * (int)sizeof(float);
    cudaFuncSetAttribute(attn_mma, cudaFuncAttributeMaxDynamicSharedMemorySize, asmem);
    attn_mma<<<dim3(NT / 128, NB * NHH), 256, asmem>>>(kpm, Cp);

    gemm_mma<1><<<gg, 256, gsmem>>>(Cp, WTp + 3 * ND * ND, out, bo);
}

// round 7
// speedup vs baseline: 1.3502x; 1.3502x over previous
#include <cuda_runtime.h>
#include <cstdint>

#define NB   2
#define NT   2048
#define ND   1024
#define NHH  16
#define NHD  64
#define NM   (NB * NT)   // 4096 rows

// Scratch (device globals: allocation is forbidden)
__device__ float g_X[NM * ND];               // tf32-rounded input, k-packed
__device__ float g_Q[NB * NHH * NT * NHD];   // [b,h,t,hd] tf32-rounded, plain
__device__ float g_K[NB * NHH * NT * NHD];
__device__ float g_V[NB * NHH * NT * NHD];
__device__ float g_C[NM * ND];               // ctx tf32-rounded, k-packed
__device__ float g_WT[4 * ND * ND];          // W^T [n][k] tf32-rounded, k-packed

// ---------------------------------------------------------------------------
// Helpers
// ---------------------------------------------------------------------------
__device__ __forceinline__ uint32_t smem_u32(const void* p) {
    uint32_t a;
    asm("{ .reg .u64 t; cvta.to.shared.u64 t, %1; cvt.u32.u64 %0, t; }"
        : "=r"(a) : "l"(p));
    return a;
}
__device__ __forceinline__ uint32_t f2tf32(float x) {
    uint32_t r; asm("cvt.rna.tf32.f32 %0, %1;" : "=r"(r) : "f"(x)); return r;
}
__device__ __forceinline__ void cpa16(uint32_t dst, const void* src) {
    asm volatile("cp.async.cg.shared.global [%0], [%1], 16;" :: "r"(dst), "l"(src));
}
#define CP_COMMIT() asm volatile("cp.async.commit_group;" ::: "memory")
#define CP_WAIT0()  asm volatile("cp.async.wait_group 0;" ::: "memory")

// pair-pack within groups of 8 along k: slot = (k&~7)|((k&3)<<1)|((k>>2)&1)
// slot order per group: k0,k4,k1,k5,k2,k6,k3,k7  -> (val[k+t], val[k+t+4]) adjacent
__device__ __forceinline__ int packk(int k) {
    return (k & ~7) | ((k & 3) << 1) | ((k >> 2) & 1);
}

// mma.sync m16n8k8 row.col tf32: d += a * b
__device__ __forceinline__ void mma8(float* d, const uint32_t* a,
                                     uint32_t b0, uint32_t b1)
{
    asm volatile(
        "mma.sync.aligned.m16n8k8.row.col.f32.tf32.tf32.f32 "
        "{%0,%1,%2,%3}, {%4,%5,%6,%7}, {%8,%9}, {%0,%1,%2,%3};"
        : "+f"(d[0]), "+f"(d[1]), "+f"(d[2]), "+f"(d[3])
        : "r"(a[0]), "r"(a[1]), "r"(a[2]), "r"(a[3]), "r"(b0), "r"(b1));
}

// ---------------------------------------------------------------------------
// Pre-round + pack x into g_X. Each thread handles one 8-float pack group.
// ---------------------------------------------------------------------------
__global__ void round_x(const float* __restrict__ src, float* __restrict__ dst)
{
    const int i = (blockIdx.x * 256 + threadIdx.x) << 3;
    float4 a = *(const float4*)(src + i);
    float4 b = *(const float4*)(src + i + 4);
    uint4 u0, u1;
    u0.x = f2tf32(a.x); u0.y = f2tf32(b.x);
    u0.z = f2tf32(a.y); u0.w = f2tf32(b.y);
    u1.x = f2tf32(a.z); u1.y = f2tf32(b.z);
    u1.z = f2tf32(a.w); u1.w = f2tf32(b.w);
    *(uint4*)(dst + i)     = u0;
    *(uint4*)(dst + i + 4) = u1;
}

// ---------------------------------------------------------------------------
// Fused weight transpose + round + pack: WT[z][n][packk(k)] = tf32(W_z[k][n])
// ---------------------------------------------------------------------------
__global__ void transpose_w4(const float* __restrict__ W0,
                             const float* __restrict__ W1,
                             const float* __restrict__ W2,
                             const float* __restrict__ W3,
                             float* __restrict__ WT)
{
    const float* W = (blockIdx.z == 0) ? W0 : (blockIdx.z == 1) ? W1
                   : (blockIdx.z == 2) ? W2 : W3;
    float* dst = WT + (size_t)blockIdx.z * ND * ND;

    __shared__ float t[32][33];
    const int x = (blockIdx.x << 5) + threadIdx.x;
    const int y0 = (blockIdx.y << 5) + threadIdx.y;
#pragma unroll
    for (int i = 0; i < 32; i += 8)
        t[threadIdx.y + i][threadIdx.x] = W[(size_t)(y0 + i) * ND + x];
    __syncthreads();
    const int x2 = (blockIdx.y << 5) + threadIdx.x;   // k index
    const int y2 = (blockIdx.x << 5) + threadIdx.y;   // n index
    const int pk = packk(x2);
#pragma unroll
    for (int i = 0; i < 32; i += 8)
        dst[(size_t)(y2 + i) * ND + pk] =
            __uint_as_float(f2tf32(t[threadIdx.x][threadIdx.y + i]));
}

// ---------------------------------------------------------------------------
// tf32 mma.sync GEMM, cp.async 2-stage, pair-packed A/B fragment loads.
// MODE 0: grid.z selects Wq/Wk/Wv; scatter to per-head [b,h,t,hd] (rounded).
// MODE 1: row-major + bias (final output, fp32).
// ---------------------------------------------------------------------------
#define GA_STR 36
template <int MODE>
__global__ void __launch_bounds__(256) gemm_mma(
    const float* __restrict__ A, const float* __restrict__ WTbase,
    float* __restrict__ O0, float* __restrict__ O1, float* __restrict__ O2,
    const float* __restrict__ bias)
{
    extern __shared__ float sm[];
    float* As = sm;             // [2][128*36]
    float* Bs = sm + 2 * 128 * GA_STR;
    const uint32_t sbase = smem_u32(sm);
    const uint32_t boff = 2 * 128 * GA_STR * 4;

    const float* BT = WTbase + (size_t)blockIdx.z * ND * ND;
    float* Out = (MODE == 1) ? O0
               : (blockIdx.z == 0 ? O0 : blockIdx.z == 1 ? O1 : O2);

    const int tid = threadIdx.x;
    const int lane = tid & 31;
    const int wid = tid >> 5;
    const int g = lane >> 2, t = lane & 3;
    const int wm = wid & 3;
    const int wn = wid >> 2;
    const int m0 = blockIdx.y << 7;
    const int n0 = blockIdx.x << 7;

    const float* Ab = A  + (size_t)m0 * ND;
    const float* Bb = BT + (size_t)n0 * ND;

    float acc[2][8][4];
#pragma unroll
    for (int mt = 0; mt < 2; ++mt)
#pragma unroll
        for (int nt = 0; nt < 8; ++nt)
#pragma unroll
            for (int e = 0; e < 4; ++e) acc[mt][nt][e] = 0.f;

    auto issue = [&](int c, int buf) {
        const int k0 = c << 5;
        const uint32_t bb = (uint32_t)buf * (128 * GA_STR * 4);
#pragma unroll
        for (int u = 0; u < 4; ++u) {
            const int f = (u << 8) + tid;
            const int row = f >> 3, kc = (f & 7) << 2;
            const uint32_t doff = bb + (uint32_t)(row * GA_STR + kc) * 4;
            cpa16(sbase + doff,        Ab + (size_t)row * ND + k0 + kc);
            cpa16(sbase + boff + doff, Bb + (size_t)row * ND + k0 + kc);
        }
        CP_COMMIT();
    };

    issue(0, 0);

    const int rb0 = wm << 5, rb1 = rb0 + 16;
    for (int c = 0; c < 32; ++c) {
        CP_WAIT0();
        __syncthreads();
        if (c < 31) issue(c + 1, (c + 1) & 1);

        const float* Ac = As + (c & 1) * (128 * GA_STR);
        const float* Bc = Bs + (c & 1) * (128 * GA_STR);
#pragma unroll
        for (int ks = 0; ks < 4; ++ks) {
            const int kb = (ks << 3) + (t << 1);   // packed float2 offset
            const float2 a00 = *(const float2*)&Ac[(rb0 + g    ) * GA_STR + kb];
            const float2 a08 = *(const float2*)&Ac[(rb0 + g + 8) * GA_STR + kb];
            const float2 a10 = *(const float2*)&Ac[(rb1 + g    ) * GA_STR + kb];
            const float2 a18 = *(const float2*)&Ac[(rb1 + g + 8) * GA_STR + kb];
            uint32_t af0[4] = {__float_as_uint(a00.x), __float_as_uint(a08.x),
                               __float_as_uint(a00.y), __float_as_uint(a08.y)};
            uint32_t af1[4] = {__float_as_uint(a10.x), __float_as_uint(a18.x),
                               __float_as_uint(a10.y), __float_as_uint(a18.y)};
#pragma unroll
            for (int nt = 0; nt < 8; ++nt) {
                const int cb = (wn << 6) + (nt << 3) + g;
                const float2 fb = *(const float2*)&Bc[cb * GA_STR + kb];
                const uint32_t b0 = __float_as_uint(fb.x);
                const uint32_t b1 = __float_as_uint(fb.y);
                mma8(acc[0][nt], af0, b0, b1);
                mma8(acc[1][nt], af1, b0, b1);
            }
        }
        __syncthreads();
    }

    // epilogue
#pragma unroll
    for (int mt = 0; mt < 2; ++mt) {
#pragma unroll
        for (int nt = 0; nt < 8; ++nt) {
            const int r0 = m0 + (wm << 5) + (mt << 4) + g;
            const int cc = n0 + (wn << 6) + (nt << 3) + (t << 1);
#pragma unroll
            for (int h = 0; h < 2; ++h) {
                const int m = r0 + (h << 3);
                float v0 = acc[mt][nt][h * 2 + 0];
                float v1 = acc[mt][nt][h * 2 + 1];
                if (MODE == 0) {
                    const int bb = m >> 11, tt = m & (NT - 1);
                    const int hh = cc >> 6, d = cc & 63;
                    float* o = Out + (((((size_t)bb * NHH + hh) * NT + tt) << 6) + d);
                    o[0] = __uint_as_float(f2tf32(v0));
                    o[1] = __uint_as_float(f2tf32(v1));
                } else {
                    float* o = Out + (size_t)m * ND + cc;
                    o[0] = v0 + bias[cc];
                    o[1] = v1 + bias[cc + 1];
                }
            }
        }
    }
}

// ---------------------------------------------------------------------------
// Causal flash attention, tf32 mma.sync (round-3 structure: 128 thr, q-tile 64).
// No cvt in hot path (inputs pre-rounded). Q frags direct from gmem.
// Writes ctx k-PACKED + tf32-rounded (consumed by MODE-1 GEMM).
// ---------------------------------------------------------------------------
#define KS_STR 68
#define VS_STR 72
__global__ void __launch_bounds__(128) attn_mma(
    const uint8_t* __restrict__ kpm, float* __restrict__ Cctx)
{
    __shared__ float Ks[64 * KS_STR];
    __shared__ float Vs[64 * VS_STR];
    __shared__ float Msk[64];

    const int tid  = threadIdx.x;
    const int lane = tid & 31;
    const int wq   = tid >> 5;               // warp's q sub-tile (16 rows)
    const int g = lane >> 2, t = lane & 3;
    const int qt = blockIdx.x;
    const int bh = blockIdx.y;
    const int bb = bh >> 4, hh = bh & 15;
    const int q0 = qt << 6;

    const float* Qg = g_Q + ((size_t)bh * NT << 6);
    const float* Kg = g_K + ((size_t)bh * NT << 6);
    const float* Vg = g_V + ((size_t)bh * NT << 6);

    // Q fragments straight from gmem (pre-rounded, plain layout)
    uint32_t qf[8][4];
    const int qr0 = q0 + (wq << 4) + g;
#pragma unroll
    for (int ks = 0; ks < 8; ++ks) {
        const int kk = ks << 3;
        qf[ks][0] = __float_as_uint(Qg[((size_t)qr0 << 6) + kk + t]);
        qf[ks][1] = __float_as_uint(Qg[((size_t)(qr0 + 8) << 6) + kk + t]);
        qf[ks][2] = __float_as_uint(Qg[((size_t)qr0 << 6) + kk + t + 4]);
        qf[ks][3] = __float_as_uint(Qg[((size_t)(qr0 + 8) << 6) + kk + t + 4]);
    }

    const int r0 = qr0, r1 = qr0 + 8;
    float m0 = -1e30f, m1 = -1e30f, l0 = 0.f, l1 = 0.f;
    float oacc[8][4];
#pragma unroll
    for (int dt = 0; dt < 8; ++dt)
#pragma unroll
        for (int e = 0; e < 4; ++e) oacc[dt][e] = 0.f;

    for (int kt = 0; kt <= qt; ++kt) {
        const int k0 = kt << 6;
        __syncthreads();   // previous iter's smem reads done
        for (int f = tid; f < 64 * 16; f += 128) {
            const int r = f >> 4, d4 = (f & 15) << 2;
            *(float4*)&Ks[r * KS_STR + d4] = *(const float4*)&Kg[((size_t)(k0 + r) << 6) + d4];
            *(float4*)&Vs[r * VS_STR + d4] = *(const float4*)&Vg[((size_t)(k0 + r) << 6) + d4];
        }
        if (tid < 64)
            Msk[tid] = kpm[bb * NT + k0 + tid] ? -1e30f : 0.f;
        __syncthreads();

        // ---- S = Q K^T ----
        float sacc[8][4];
#pragma unroll
        for (int nt = 0; nt < 8; ++nt)
#pragma unroll
            for (int e = 0; e < 4; ++e) sacc[nt][e] = 0.f;

#pragma unroll
        for (int ks = 0; ks < 8; ++ks) {
            const int kk = ks << 3;
#pragma unroll
            for (int nt = 0; nt < 8; ++nt) {
                const int kr = (nt << 3) + g;
                const uint32_t b0 = __float_as_uint(Ks[kr * KS_STR + kk + t]);
                const uint32_t b1 = __float_as_uint(Ks[kr * KS_STR + kk + t + 4]);
                mma8(sacc[nt], qf[ks], b0, b1);
            }
        }

        // ---- scale + masks ----
        const bool diag = (kt == qt);
        float mx0 = -1e30f, mx1 = -1e30f;
#pragma unroll
        for (int nt = 0; nt < 8; ++nt) {
            const int cl = (nt << 3) + (t << 1);
            const int kv0 = k0 + cl, kv1 = kv0 + 1;
            const float pm0 = Msk[cl], pm1 = Msk[cl + 1];
            float s0 = sacc[nt][0] * 0.125f + pm0;
            float s1 = sacc[nt][1] * 0.125f + pm1;
            float s2 = sacc[nt][2] * 0.125f + pm0;
            float s3 = sacc[nt][3] * 0.125f + pm1;
            if (diag) {
                if (kv0 > r0) s0 = -1e30f;
                if (kv1 > r0) s1 = -1e30f;
                if (kv0 > r1) s2 = -1e30f;
                if (kv1 > r1) s3 = -1e30f;
            }
            sacc[nt][0] = s0; sacc[nt][1] = s1;
            sacc[nt][2] = s2; sacc[nt][3] = s3;
            mx0 = fmaxf(mx0, fmaxf(s0, s1));
            mx1 = fmaxf(mx1, fmaxf(s2, s3));
        }
        mx0 = fmaxf(mx0, __shfl_xor_sync(0xffffffffu, mx0, 1));
        mx0 = fmaxf(mx0, __shfl_xor_sync(0xffffffffu, mx0, 2));
        mx1 = fmaxf(mx1, __shfl_xor_sync(0xffffffffu, mx1, 1));
        mx1 = fmaxf(mx1, __shfl_xor_sync(0xffffffffu, mx1, 2));

        const float nm0 = fmaxf(m0, mx0), nm1 = fmaxf(m1, mx1);
        const float cr0 = __expf(m0 - nm0), cr1 = __expf(m1 - nm1);
        m0 = nm0; m1 = nm1;

        float sum0 = 0.f, sum1 = 0.f;
#pragma unroll
        for (int nt = 0; nt < 8; ++nt) {
            float p0 = __expf(sacc[nt][0] - nm0);
            float p1 = __expf(sacc[nt][1] - nm0);
            float p2 = __expf(sacc[nt][2] - nm1);
            float p3 = __expf(sacc[nt][3] - nm1);
            sacc[nt][0] = p0; sacc[nt][1] = p1;
            sacc[nt][2] = p2; sacc[nt][3] = p3;
            sum0 += p0 + p1; sum1 += p2 + p3;
        }
        sum0 += __shfl_xor_sync(0xffffffffu, sum0, 1);
        sum0 += __shfl_xor_sync(0xffffffffu, sum0, 2);
        sum1 += __shfl_xor_sync(0xffffffffu, sum1, 1);
        sum1 += __shfl_xor_sync(0xffffffffu, sum1, 2);
        l0 = l0 * cr0 + sum0;
        l1 = l1 * cr1 + sum1;
#pragma unroll
        for (int dt = 0; dt < 8; ++dt) {
            oacc[dt][0] *= cr0; oacc[dt][1] *= cr0;
            oacc[dt][2] *= cr1; oacc[dt][3] *= cr1;
        }

        // ---- O += P V ----  (C-frag -> A-frag via quad shfls)
        const int srcA = (lane & ~3) | (t >> 1);
        const int srcB = srcA + 2;
        const bool odd = (t & 1);
#pragma unroll
        for (int kk = 0; kk < 8; ++kk) {
            const float pA0 = __shfl_sync(0xffffffffu, sacc[kk][0], srcA);
            const float pA1 = __shfl_sync(0xffffffffu, sacc[kk][1], srcA);
            const float pB0 = __shfl_sync(0xffffffffu, sacc[kk][0], srcB);
            const float pB1 = __shfl_sync(0xffffffffu, sacc[kk][1], srcB);
            const float pC0 = __shfl_sync(0xffffffffu, sacc[kk][2], srcA);
            const float pC1 = __shfl_sync(0xffffffffu, sacc[kk][3], srcA);
            const float pD0 = __shfl_sync(0xffffffffu, sacc[kk][2], srcB);
            const float pD1 = __shfl_sync(0xffffffffu, sacc[kk][3], srcB);
            uint32_t a[4];
            a[0] = f2tf32(odd ? pA1 : pA0);
            a[1] = f2tf32(odd ? pC1 : pC0);
            a[2] = f2tf32(odd ? pB1 : pB0);
            a[3] = f2tf32(odd ? pD1 : pD0);
#pragma unroll
            for (int dt = 0; dt < 8; ++dt) {
                const int dc = (dt << 3) + g;
                const uint32_t b0 = __float_as_uint(Vs[((kk << 3) + t    ) * VS_STR + dc]);
                const uint32_t b1 = __float_as_uint(Vs[((kk << 3) + t + 4) * VS_STR + dc]);
                mma8(oacc[dt], a, b0, b1);
            }
        }
    }

    // ---- normalize + write ctx [b*T+t, packk(h*64+d)], tf32-rounded ----
    const float i0 = 1.f / l0, i1 = 1.f / l1;
    const int mrow0 = (bb << 11) + q0 + (wq << 4) + g;
#pragma unroll
    for (int dt = 0; dt < 8; ++dt) {
        const int dc = (hh << 6) + (dt << 3) + (t << 1);
        const int p0 = packk(dc), p1 = packk(dc + 1);
        float* o0 = Cctx + (size_t)mrow0 * ND;
        float* o1 = Cctx + (size_t)(mrow0 + 8) * ND;
        o0[p0] = __uint_as_float(f2tf32(oacc[dt][0] * i0));
        o0[p1] = __uint_as_float(f2tf32(oacc[dt][1] * i0));
        o1[p0] = __uint_as_float(f2tf32(oacc[dt][2] * i1));
        o1[p1] = __uint_as_float(f2tf32(oacc[dt][3] * i1));
    }
}

// ---------------------------------------------------------------------------
extern "C" void kernel_launch(void* const* d_in, const int* in_sizes, int n_in,
                              void* d_out, int out_size)
{
    (void)in_sizes; (void)n_in; (void)out_size;
    const float*   x   = (const float*)d_in[0];
    const float*   Wq  = (const float*)d_in[1];
    const float*   Wk  = (const float*)d_in[2];
    const float*   Wv  = (const float*)d_in[3];
    const float*   Wo  = (const float*)d_in[4];
    const float*   bo  = (const float*)d_in[5];
    const uint8_t* kpm = (const uint8_t*)d_in[6];
    float* out = (float*)d_out;

    float *Xp, *Qp, *Kp, *Vp, *Cp, *WTp;
    cudaGetSymbolAddress((void**)&Xp, g_X);
    cudaGetSymbolAddress((void**)&Qp, g_Q);
    cudaGetSymbolAddress((void**)&Kp, g_K);
    cudaGetSymbolAddress((void**)&Vp, g_V);
    cudaGetSymbolAddress((void**)&Cp, g_C);
    cudaGetSymbolAddress((void**)&WTp, g_WT);

    round_x<<<(NM * ND) / (256 * 8), 256>>>(x, Xp);
    transpose_w4<<<dim3(32, 32, 4), dim3(32, 8)>>>(Wq, Wk, Wv, Wo, WTp);

    const int gsmem = 2 * 2 * 128 * GA_STR * (int)sizeof(float);  // 73728
    cudaFuncSetAttribute(gemm_mma<0>, cudaFuncAttributeMaxDynamicSharedMemorySize, gsmem);
    cudaFuncSetAttribute(gemm_mma<1>, cudaFuncAttributeMaxDynamicSharedMemorySize, gsmem);

    // fused Q/K/V projections: grid.z selects the weight + destination
    gemm_mma<0><<<dim3(ND / 128, NM / 128, 3), 256, gsmem>>>(
        Xp, WTp, Qp, Kp, Vp, nullptr);

    attn_mma<<<dim3(NT / 64, NB * NHH), 128>>>(kpm, Cp);

    gemm_mma<1><<<dim3(ND / 128, NM / 128, 1), 256, gsmem>>>(
        Cp, WTp + 3 * (size_t)ND * ND, out, nullptr, nullptr, bo);
}

// round 9
// speedup vs baseline: 1.4452x; 1.0704x over previous
#include <cuda_runtime.h>
#include <cstdint>

#define NB   2
#define NT   2048
#define ND   1024
#define NHH  16
#define NHD  64
#define NM   (NB * NT)   // 4096 rows

// Scratch (device globals: allocation is forbidden)
__device__ float g_X[NM * ND];               // tf32-rounded input, k-packed
__device__ float g_Q[NB * NHH * NT * NHD];   // [b,h,t,packd(d)]
__device__ float g_K[NB * NHH * NT * NHD];   // [b,h,t,packd(d)]
__device__ float g_V[NB * NHH * NT * NHD];   // [b,h,d,packd(t)]  (transposed!)
__device__ float g_C[NM * ND];               // ctx tf32-rounded, k-packed
__device__ float g_WT[4 * ND * ND];          // W^T [n][k] tf32-rounded, k-packed

// ---------------------------------------------------------------------------
// Helpers
// ---------------------------------------------------------------------------
__device__ __forceinline__ uint32_t smem_u32(const void* p) {
    uint32_t a;
    asm("{ .reg .u64 t; cvta.to.shared.u64 t, %1; cvt.u32.u64 %0, t; }"
        : "=r"(a) : "l"(p));
    return a;
}
__device__ __forceinline__ uint32_t f2tf32(float x) {
    uint32_t r; asm("cvt.rna.tf32.f32 %0, %1;" : "=r"(r) : "f"(x)); return r;
}
__device__ __forceinline__ void cpa16(uint32_t dst, const void* src) {
    asm volatile("cp.async.cg.shared.global [%0], [%1], 16;" :: "r"(dst), "l"(src));
}
#define CP_COMMIT() asm volatile("cp.async.commit_group;" ::: "memory")
#define CP_WAIT0()  asm volatile("cp.async.wait_group 0;" ::: "memory")

// pair-pack within groups of 8: slot = (k&~7)|((k&3)<<1)|((k>>2)&1)
// order per group: k0,k4,k1,k5,k2,k6,k3,k7 -> (v[j], v[j+4]) adjacent
__device__ __forceinline__ int packk(int k) {
    return (k & ~7) | ((k & 3) << 1) | ((k >> 2) & 1);
}

// mma.sync m16n8k8 row.col tf32: d += a * b
__device__ __forceinline__ void mma8(float* d, const uint32_t* a,
                                     uint32_t b0, uint32_t b1)
{
    asm volatile(
        "mma.sync.aligned.m16n8k8.row.col.f32.tf32.tf32.f32 "
        "{%0,%1,%2,%3}, {%4,%5,%6,%7}, {%8,%9}, {%0,%1,%2,%3};"
        : "+f"(d[0]), "+f"(d[1]), "+f"(d[2]), "+f"(d[3])
        : "r"(a[0]), "r"(a[1]), "r"(a[2]), "r"(a[3]), "r"(b0), "r"(b1));
}

// ---------------------------------------------------------------------------
// Pre-round + pack x into g_X (one 8-group per thread).
// ---------------------------------------------------------------------------
__global__ void round_x(const float* __restrict__ src, float* __restrict__ dst)
{
    const int i = (blockIdx.x * 256 + threadIdx.x) << 3;
    float4 a = *(const float4*)(src + i);
    float4 b = *(const float4*)(src + i + 4);
    uint4 u0, u1;
    u0.x = f2tf32(a.x); u0.y = f2tf32(b.x);
    u0.z = f2tf32(a.y); u0.w = f2tf32(b.y);
    u1.x = f2tf32(a.z); u1.y = f2tf32(b.z);
    u1.z = f2tf32(a.w); u1.w = f2tf32(b.w);
    *(uint4*)(dst + i)     = u0;
    *(uint4*)(dst + i + 4) = u1;
}

// ---------------------------------------------------------------------------
// Fused weight transpose + round + pack: WT[z][n][packk(k)] = tf32(W_z[k][n])
// ---------------------------------------------------------------------------
__global__ void transpose_w4(const float* __restrict__ W0,
                             const float* __restrict__ W1,
                             const float* __restrict__ W2,
                             const float* __restrict__ W3,
                             float* __restrict__ WT)
{
    const float* W = (blockIdx.z == 0) ? W0 : (blockIdx.z == 1) ? W1
                   : (blockIdx.z == 2) ? W2 : W3;
    float* dst = WT + (size_t)blockIdx.z * ND * ND;

    __shared__ float t[32][33];
    const int x = (blockIdx.x << 5) + threadIdx.x;
    const int y0 = (blockIdx.y << 5) + threadIdx.y;
#pragma unroll
    for (int i = 0; i < 32; i += 8)
        t[threadIdx.y + i][threadIdx.x] = W[(size_t)(y0 + i) * ND + x];
    __syncthreads();
    const int x2 = (blockIdx.y << 5) + threadIdx.x;   // k index
    const int y2 = (blockIdx.x << 5) + threadIdx.y;   // n index
    const int pk = packk(x2);
#pragma unroll
    for (int i = 0; i < 32; i += 8)
        dst[(size_t)(y2 + i) * ND + pk] =
            __uint_as_float(f2tf32(t[threadIdx.x][threadIdx.y + i]));
}

// ---------------------------------------------------------------------------
// tf32 mma.sync GEMM, cp.async 2-stage (single sync/chunk), packed frag loads.
// MODE 0: grid.z=0/1 -> Q/K per-head [b,h,t,packd(d)];
//         grid.z=2   -> V transposed [b,h,d,packd(t)]. All tf32-rounded.
// MODE 1: row-major + bias (final output, fp32).
// ---------------------------------------------------------------------------
#define GA_STR 36
template <int MODE>
__global__ void __launch_bounds__(256) gemm_mma(
    const float* __restrict__ A, const float* __restrict__ WTbase,
    float* __restrict__ O0, float* __restrict__ O1, float* __restrict__ O2,
    const float* __restrict__ bias)
{
    extern __shared__ float sm[];
    float* As = sm;             // [2][128*36]
    float* Bs = sm + 2 * 128 * GA_STR;
    const uint32_t sbase = smem_u32(sm);
    const uint32_t boff = 2 * 128 * GA_STR * 4;

    const float* BT = WTbase + (size_t)blockIdx.z * ND * ND;
    float* Out = (MODE == 1) ? O0
               : (blockIdx.z == 0 ? O0 : blockIdx.z == 1 ? O1 : O2);

    const int tid = threadIdx.x;
    const int lane = tid & 31;
    const int wid = tid >> 5;
    const int g = lane >> 2, t = lane & 3;
    const int wm = wid & 3;
    const int wn = wid >> 2;
    const int m0 = blockIdx.y << 7;
    const int n0 = blockIdx.x << 7;

    const float* Ab = A  + (size_t)m0 * ND;
    const float* Bb = BT + (size_t)n0 * ND;

    float acc[2][8][4];
#pragma unroll
    for (int mt = 0; mt < 2; ++mt)
#pragma unroll
        for (int nt = 0; nt < 8; ++nt)
#pragma unroll
            for (int e = 0; e < 4; ++e) acc[mt][nt][e] = 0.f;

    auto issue = [&](int c, int buf) {
        const int k0 = c << 5;
        const uint32_t bb = (uint32_t)buf * (128 * GA_STR * 4);
#pragma unroll
        for (int u = 0; u < 4; ++u) {
            const int f = (u << 8) + tid;
            const int row = f >> 3, kc = (f & 7) << 2;
            const uint32_t doff = bb + (uint32_t)(row * GA_STR + kc) * 4;
            cpa16(sbase + doff,        Ab + (size_t)row * ND + k0 + kc);
            cpa16(sbase + boff + doff, Bb + (size_t)row * ND + k0 + kc);
        }
        CP_COMMIT();
    };

    issue(0, 0);

    const int rb0 = wm << 5, rb1 = rb0 + 16;
    for (int c = 0; c < 32; ++c) {
        CP_WAIT0();
        __syncthreads();
        if (c < 31) issue(c + 1, (c + 1) & 1);

        const float* Ac = As + (c & 1) * (128 * GA_STR);
        const float* Bc = Bs + (c & 1) * (128 * GA_STR);
#pragma unroll
        for (int ks = 0; ks < 4; ++ks) {
            const int kb = (ks << 3) + (t << 1);   // packed float2 offset
            const float2 a00 = *(const float2*)&Ac[(rb0 + g    ) * GA_STR + kb];
            const float2 a08 = *(const float2*)&Ac[(rb0 + g + 8) * GA_STR + kb];
            const float2 a10 = *(const float2*)&Ac[(rb1 + g    ) * GA_STR + kb];
            const float2 a18 = *(const float2*)&Ac[(rb1 + g + 8) * GA_STR + kb];
            uint32_t af0[4] = {__float_as_uint(a00.x), __float_as_uint(a08.x),
                               __float_as_uint(a00.y), __float_as_uint(a08.y)};
            uint32_t af1[4] = {__float_as_uint(a10.x), __float_as_uint(a18.x),
                               __float_as_uint(a10.y), __float_as_uint(a18.y)};
#pragma unroll
            for (int nt = 0; nt < 8; ++nt) {
                const int cb = (wn << 6) + (nt << 3) + g;
                const float2 fb = *(const float2*)&Bc[cb * GA_STR + kb];
                const uint32_t b0 = __float_as_uint(fb.x);
                const uint32_t b1 = __float_as_uint(fb.y);
                mma8(acc[0][nt], af0, b0, b1);
                mma8(acc[1][nt], af1, b0, b1);
            }
        }
        // no trailing sync: next iter's wait+sync orders buffer reuse
    }

    // epilogue
#pragma unroll
    for (int mt = 0; mt < 2; ++mt) {
#pragma unroll
        for (int nt = 0; nt < 8; ++nt) {
            const int r0 = m0 + (wm << 5) + (mt << 4) + g;
            const int cc = n0 + (wn << 6) + (nt << 3) + (t << 1);
#pragma unroll
            for (int h = 0; h < 2; ++h) {
                const int m = r0 + (h << 3);
                float v0 = acc[mt][nt][h * 2 + 0];
                float v1 = acc[mt][nt][h * 2 + 1];
                if (MODE == 0) {
                    const int bb = m >> 11, tt = m & (NT - 1);
                    const int hh = cc >> 6, d = cc & 63;
                    if (blockIdx.z == 2) {
                        // V transposed: [b,h,d,packd(t)]
                        float* vb = Out + ((((size_t)bb * NHH + hh) * NHD) * NT)
                                        + (size_t)packk(tt) ;
                        vb[(size_t)d * NT]       = __uint_as_float(f2tf32(v0));
                        vb[(size_t)(d + 1) * NT] = __uint_as_float(f2tf32(v1));
                    } else {
                        float* o = Out + (((((size_t)bb * NHH + hh) * NT + tt) << 6));
                        o[packk(d)]     = __uint_as_float(f2tf32(v0));
                        o[packk(d + 1)] = __uint_as_float(f2tf32(v1));
                    }
                } else {
                    float* o = Out + (size_t)m * ND + cc;
                    o[0] = v0 + bias[cc];
                    o[1] = v1 + bias[cc + 1];
                }
            }
        }
    }
}

// ---------------------------------------------------------------------------
// Causal flash attention, tf32 mma.sync, 128 thr, q-tile 64.
// K smem [t][packd(d)] stride 72; V smem [d][packd(t)] stride 72.
// All B-fragments are single LDS.64. LPT block order. cp.async loads.
// ---------------------------------------------------------------------------
#define KS_STR 72
#define VS_STR 72
__global__ void __launch_bounds__(128) attn_mma(
    const uint8_t* __restrict__ kpm, float* __restrict__ Cctx)
{
    __shared__ float Ks[64 * KS_STR];
    __shared__ float Vs[64 * VS_STR];
    __shared__ float Msk[64];
    const uint32_t kbase = smem_u32(Ks);
    const uint32_t vbase = smem_u32(Vs);

    const int tid  = threadIdx.x;
    const int lane = tid & 31;
    const int wq   = tid >> 5;               // warp's q sub-tile (16 rows)
    const int g = lane >> 2, t = lane & 3;
    const int qt = (int)(gridDim.x - 1) - (int)blockIdx.x;   // LPT order
    const int bh = blockIdx.y;
    const int bb = bh >> 4, hh = bh & 15;
    const int q0 = qt << 6;

    const float* Qg = g_Q + ((size_t)bh * NT << 6);
    const float* Kg = g_K + ((size_t)bh * NT << 6);
    const float* Vg = g_V + ((size_t)bh << 6) * NT;   // [d][packd(t)] rows

    // Q fragments from gmem (packed d: pairs (k, k+4) adjacent)
    uint32_t qf[8][4];
    const int qr0 = q0 + (wq << 4) + g;
#pragma unroll
    for (int ks = 0; ks < 8; ++ks) {
        const int kk = (ks << 3) + (t << 1);
        const float2 qa = *(const float2*)&Qg[((size_t)qr0 << 6) + kk];
        const float2 qb = *(const float2*)&Qg[((size_t)(qr0 + 8) << 6) + kk];
        qf[ks][0] = __float_as_uint(qa.x);
        qf[ks][1] = __float_as_uint(qb.x);
        qf[ks][2] = __float_as_uint(qa.y);
        qf[ks][3] = __float_as_uint(qb.y);
    }

    const int r0 = qr0, r1 = qr0 + 8;
    float m0 = -1e30f, m1 = -1e30f, l0 = 0.f, l1 = 0.f;
    float oacc[8][4];
#pragma unroll
    for (int dt = 0; dt < 8; ++dt)
#pragma unroll
        for (int e = 0; e < 4; ++e) oacc[dt][e] = 0.f;

    for (int kt = 0; kt <= qt; ++kt) {
        const int k0 = kt << 6;
        __syncthreads();   // previous tile's smem reads done
#pragma unroll
        for (int u = 0; u < 8; ++u) {
            const int f = (u << 7) + tid;
            const int r = f >> 4, s4 = (f & 15) << 2;
            cpa16(kbase + (uint32_t)(r * KS_STR + s4) * 4,
                  Kg + ((size_t)(k0 + r) << 6) + s4);
            cpa16(vbase + (uint32_t)(r * VS_STR + s4) * 4,
                  Vg + (size_t)r * NT + k0 + s4);
        }
        CP_COMMIT();
        if (tid < 64)
            Msk[tid] = kpm[bb * NT + k0 + tid] ? -1e30f : 0.f;
        CP_WAIT0();
        __syncthreads();

        // ---- S = Q K^T ----  (B-frag: one LDS.64 per mma)
        float sacc[8][4];
#pragma unroll
        for (int nt = 0; nt < 8; ++nt)
#pragma unroll
            for (int e = 0; e < 4; ++e) sacc[nt][e] = 0.f;

#pragma unroll
        for (int ks = 0; ks < 8; ++ks) {
            const int kk = (ks << 3) + (t << 1);
#pragma unroll
            for (int nt = 0; nt < 8; ++nt) {
                const int kr = (nt << 3) + g;
                const float2 kb = *(const float2*)&Ks[kr * KS_STR + kk];
                mma8(sacc[nt], qf[ks],
                     __float_as_uint(kb.x), __float_as_uint(kb.y));
            }
        }

        // ---- scale + masks ----
        const bool diag = (kt == qt);
        float mx0 = -1e30f, mx1 = -1e30f;
#pragma unroll
        for (int nt = 0; nt < 8; ++nt) {
            const int cl = (nt << 3) + (t << 1);
            const int kv0 = k0 + cl, kv1 = kv0 + 1;
            const float pm0 = Msk[cl], pm1 = Msk[cl + 1];
            float s0 = sacc[nt][0] * 0.125f + pm0;
            float s1 = sacc[nt][1] * 0.125f + pm1;
            float s2 = sacc[nt][2] * 0.125f + pm0;
            float s3 = sacc[nt][3] * 0.125f + pm1;
            if (diag) {
                if (kv0 > r0) s0 = -1e30f;
                if (kv1 > r0) s1 = -1e30f;
                if (kv0 > r1) s2 = -1e30f;
                if (kv1 > r1) s3 = -1e30f;
            }
            sacc[nt][0] = s0; sacc[nt][1] = s1;
            sacc[nt][2] = s2; sacc[nt][3] = s3;
            mx0 = fmaxf(mx0, fmaxf(s0, s1));
            mx1 = fmaxf(mx1, fmaxf(s2, s3));
        }
        mx0 = fmaxf(mx0, __shfl_xor_sync(0xffffffffu, mx0, 1));
        mx0 = fmaxf(mx0, __shfl_xor_sync(0xffffffffu, mx0, 2));
        mx1 = fmaxf(mx1, __shfl_xor_sync(0xffffffffu, mx1, 1));
        mx1 = fmaxf(mx1, __shfl_xor_sync(0xffffffffu, mx1, 2));

        const float nm0 = fmaxf(m0, mx0), nm1 = fmaxf(m1, mx1);
        const float cr0 = __expf(m0 - nm0), cr1 = __expf(m1 - nm1);
        m0 = nm0; m1 = nm1;

        float sum0 = 0.f, sum1 = 0.f;
#pragma unroll
        for (int nt = 0; nt < 8; ++nt) {
            float p0 = __expf(sacc[nt][0] - nm0);
            float p1 = __expf(sacc[nt][1] - nm0);
            float p2 = __expf(sacc[nt][2] - nm1);
            float p3 = __expf(sacc[nt][3] - nm1);
            sacc[nt][0] = p0; sacc[nt][1] = p1;
            sacc[nt][2] = p2; sacc[nt][3] = p3;
            sum0 += p0 + p1; sum1 += p2 + p3;
        }
        sum0 += __shfl_xor_sync(0xffffffffu, sum0, 1);
        sum0 += __shfl_xor_sync(0xffffffffu, sum0, 2);
        sum1 += __shfl_xor_sync(0xffffffffu, sum1, 1);
        sum1 += __shfl_xor_sync(0xffffffffu, sum1, 2);
        l0 = l0 * cr0 + sum0;
        l1 = l1 * cr1 + sum1;
#pragma unroll
        for (int dt = 0; dt < 8; ++dt) {
            oacc[dt][0] *= cr0; oacc[dt][1] *= cr0;
            oacc[dt][2] *= cr1; oacc[dt][3] *= cr1;
        }

        // ---- O += P V ----  (C-frag -> A-frag via quad shfls; V B-frag LDS.64)
        const int srcA = (lane & ~3) | (t >> 1);
        const int srcB = srcA + 2;
        const bool odd = (t & 1);
#pragma unroll
        for (int kk = 0; kk < 8; ++kk) {
            const float pA0 = __shfl_sync(0xffffffffu, sacc[kk][0], srcA);
            const float pA1 = __shfl_sync(0xffffffffu, sacc[kk][1], srcA);
            const float pB0 = __shfl_sync(0xffffffffu, sacc[kk][0], srcB);
            const float pB1 = __shfl_sync(0xffffffffu, sacc[kk][1], srcB);
            const float pC0 = __shfl_sync(0xffffffffu, sacc[kk][2], srcA);
            const float pC1 = __shfl_sync(0xffffffffu, sacc[kk][3], srcA);
            const float pD0 = __shfl_sync(0xffffffffu, sacc[kk][2], srcB);
            const float pD1 = __shfl_sync(0xffffffffu, sacc[kk][3], srcB);
            uint32_t a[4];
            a[0] = f2tf32(odd ? pA1 : pA0);
            a[1] = f2tf32(odd ? pC1 : pC0);
            a[2] = f2tf32(odd ? pB1 : pB0);
            a[3] = f2tf32(odd ? pD1 : pD0);
            const int kc = (kk << 3) + (t << 1);
#pragma unroll
            for (int dt = 0; dt < 8; ++dt) {
                const int dc = (dt << 3) + g;
                const float2 vb = *(const float2*)&Vs[dc * VS_STR + kc];
                mma8(oacc[dt], a,
                     __float_as_uint(vb.x), __float_as_uint(vb.y));
            }
        }
    }

    // ---- normalize + write ctx [b*T+t, packk(h*64+d)], tf32-rounded ----
    const float i0 = 1.f / l0, i1 = 1.f / l1;
    const int mrow0 = (bb << 11) + q0 + (wq << 4) + g;
#pragma unroll
    for (int dt = 0; dt < 8; ++dt) {
        const int dc = (hh << 6) + (dt << 3) + (t << 1);
        const int p0 = packk(dc), p1 = packk(dc + 1);
        float* o0 = Cctx + (size_t)mrow0 * ND;
        float* o1 = Cctx + (size_t)(mrow0 + 8) * ND;
        o0[p0] = __uint_as_float(f2tf32(oacc[dt][0] * i0));
        o0[p1] = __uint_as_float(f2tf32(oacc[dt][1] * i0));
        o1[p0] = __uint_as_float(f2tf32(oacc[dt][2] * i1));
        o1[p1] = __uint_as_float(f2tf32(oacc[dt][3] * i1));
    }
}

// ---------------------------------------------------------------------------
extern "C" void kernel_launch(void* const* d_in, const int* in_sizes, int n_in,
                              void* d_out, int out_size)
{
    (void)in_sizes; (void)n_in; (void)out_size;
    const float*   x   = (const float*)d_in[0];
    const float*   Wq  = (const float*)d_in[1];
    const float*   Wk  = (const float*)d_in[2];
    const float*   Wv  = (const float*)d_in[3];
    const float*   Wo  = (const float*)d_in[4];
    const float*   bo  = (const float*)d_in[5];
    const uint8_t* kpm = (const uint8_t*)d_in[6];
    float* out = (float*)d_out;

    float *Xp, *Qp, *Kp, *Vp, *Cp, *WTp;
    cudaGetSymbolAddress((void**)&Xp, g_X);
    cudaGetSymbolAddress((void**)&Qp, g_Q);
    cudaGetSymbolAddress((void**)&Kp, g_K);
    cudaGetSymbolAddress((void**)&Vp, g_V);
    cudaGetSymbolAddress((void**)&Cp, g_C);
    cudaGetSymbolAddress((void**)&WTp, g_WT);

    round_x<<<(NM * ND) / (256 * 8), 256>>>(x, Xp);
    transpose_w4<<<dim3(32, 32, 4), dim3(32, 8)>>>(Wq, Wk, Wv, Wo, WTp);

    const int gsmem = 2 * 2 * 128 * GA_STR * (int)sizeof(float);  // 73728
    cudaFuncSetAttribute(gemm_mma<0>, cudaFuncAttributeMaxDynamicSharedMemorySize, gsmem);
    cudaFuncSetAttribute(gemm_mma<1>, cudaFuncAttributeMaxDynamicSharedMemorySize, gsmem);

    // fused Q/K/V projections: grid.z selects the weight + destination/layout
    gemm_mma<0><<<dim3(ND / 128, NM / 128, 3), 256, gsmem>>>(
        Xp, WTp, Qp, Kp, Vp, nullptr);

    attn_mma<<<dim3(NT / 64, NB * NHH), 128>>>(kpm, Cp);

    gemm_mma<1><<<dim3(ND / 128, NM / 128, 1), 256, gsmem>>>(
        Cp, WTp + 3 * (size_t)ND * ND, out, nullptr, nullptr, bo);
}

// round 13
// speedup vs baseline: 2.8175x; 1.9495x over previous
#include <cuda_runtime.h>
#include <cuda_fp16.h>
#include <cstdint>

#define NB   2
#define NT   2048
#define ND   1024
#define NHH  16
#define NHD  64
#define NM   (NB * NT)   // 4096 rows

// Scratch (device globals: allocation is forbidden). All fp16, pair-packed.
__device__ __half g_X[NM * ND];               // input, k word-packed
__device__ __half g_Q[NB * NHH * NT * NHD];   // [b,h,t,packh(d)]
__device__ __half g_K[NB * NHH * NT * NHD];   // [b,h,t,packh(d)]
__device__ __half g_V[NB * NHH * NT * NHD];   // [b,h,d,packh(t)] (transposed)
__device__ __half g_C[NM * ND];               // ctx, k word-packed
__device__ __half g_WT[4 * ND * ND];          // W^T [n][k] word-packed

// ---------------------------------------------------------------------------
// Helpers
// ---------------------------------------------------------------------------
__device__ __forceinline__ uint32_t smem_u32(const void* p) {
    uint32_t a;
    asm("{ .reg .u64 t; cvta.to.shared.u64 t, %1; cvt.u32.u64 %0, t; }"
        : "=r"(a) : "l"(p));
    return a;
}
__device__ __forceinline__ uint32_t h2pack(float lo, float hi) {
    __half2 h = __floats2half2_rn(lo, hi);
    return *reinterpret_cast<uint32_t*>(&h);
}
__device__ __forceinline__ void cpa16(uint32_t dst, const void* src) {
    asm volatile("cp.async.cg.shared.global [%0], [%1], 16;" :: "r"(dst), "l"(src));
}
#define CP_COMMIT() asm volatile("cp.async.commit_group;" ::: "memory")
#define CP_WAIT0()  asm volatile("cp.async.wait_group 0;" ::: "memory")

// half-index pack within groups of 16 halves (8 words): word j -> slot
// ((j&3)<<1)|((j>>2)&1). Packed order of k: 0,1,8,9,2,3,10,11,4,5,12,13,6,7,14,15
// => an LDS.64 at word offset 2t yields halves (2t,2t+1),(2t+8,2t+9) = the
// m16n8k16 fragment pairs.
__device__ __forceinline__ int packh(int k) {
    const int j = (k >> 1) & 7;
    return (k & ~15) | (((((j & 3) << 1) | ((j >> 2) & 1))) << 1) | (k & 1);
}

// mma.sync m16n8k16 row.col fp16 -> f32: d += a * b
__device__ __forceinline__ void mma16(float* d, const uint32_t* a,
                                      uint32_t b0, uint32_t b1)
{
    asm volatile(
        "mma.sync.aligned.m16n8k16.row.col.f32.f16.f16.f32 "
        "{%0,%1,%2,%3}, {%4,%5,%6,%7}, {%8,%9}, {%0,%1,%2,%3};"
        : "+f"(d[0]), "+f"(d[1]), "+f"(d[2]), "+f"(d[3])
        : "r"(a[0]), "r"(a[1]), "r"(a[2]), "r"(a[3]), "r"(b0), "r"(b1));
}

// ---------------------------------------------------------------------------
// x (f32) -> g_X (f16, word-packed). One 16-half group per thread.
// ---------------------------------------------------------------------------
__global__ void round_x(const float* __restrict__ src, __half* __restrict__ dst)
{
    const int gid = blockIdx.x * 256 + threadIdx.x;
    const int i = gid << 4;
    const float4 f0 = *(const float4*)(src + i);
    const float4 f1 = *(const float4*)(src + i + 4);
    const float4 f2 = *(const float4*)(src + i + 8);
    const float4 f3 = *(const float4*)(src + i + 12);
    uint4 w0, w1;
    w0.x = h2pack(f0.x, f0.y); w0.y = h2pack(f2.x, f2.y);
    w0.z = h2pack(f0.z, f0.w); w0.w = h2pack(f2.z, f2.w);
    w1.x = h2pack(f1.x, f1.y); w1.y = h2pack(f3.x, f3.y);
    w1.z = h2pack(f1.z, f1.w); w1.w = h2pack(f3.z, f3.w);
    ((uint4*)dst)[gid * 2]     = w0;
    ((uint4*)dst)[gid * 2 + 1] = w1;
}

// ---------------------------------------------------------------------------
// Weight transpose + f16 + pack: WT[z][n][packh(k)] = f16(W_z[k][n])
// ---------------------------------------------------------------------------
__global__ void transpose_w4(const float* __restrict__ W0,
                             const float* __restrict__ W1,
                             const float* __restrict__ W2,
                             const float* __restrict__ W3,
                             __half* __restrict__ WT)
{
    const float* W = (blockIdx.z == 0) ? W0 : (blockIdx.z == 1) ? W1
                   : (blockIdx.z == 2) ? W2 : W3;
    __half* dst = WT + (size_t)blockIdx.z * ND * ND;

    __shared__ float t[32][33];
    const int x = (blockIdx.x << 5) + threadIdx.x;
    const int y0 = (blockIdx.y << 5) + threadIdx.y;
#pragma unroll
    for (int i = 0; i < 32; i += 8)
        t[threadIdx.y + i][threadIdx.x] = W[(size_t)(y0 + i) * ND + x];
    __syncthreads();
    const int x2 = (blockIdx.y << 5) + threadIdx.x;   // k
    const int y2 = (blockIdx.x << 5) + threadIdx.y;   // n
    const int pk = packh(x2);
#pragma unroll
    for (int i = 0; i < 32; i += 8)
        dst[(size_t)(y2 + i) * ND + pk] = __float2half_rn(t[threadIdx.x][threadIdx.y + i]);
}

// ---------------------------------------------------------------------------
// fp16 m16n8k16 GEMM, cp.async 2-stage, single sync/chunk.
// 128x128 tile, BK=32 halves (2 k16 steps), 8 warps (4m x 2n), warp 32x64.
// MODE 0: grid.z 0/1 -> Q/K [b,h,t,packh(d)]; z=2 -> V [b,h,d,packh(t)].
// MODE 1: f32 row-major + bias (final output).
// ---------------------------------------------------------------------------
#define GW 24     // smem words per row (16 data + 8 pad) - conflict-free
template <int MODE>
__global__ void __launch_bounds__(256) gemm_mma(
    const __half* __restrict__ A, const __half* __restrict__ WTbase,
    __half* __restrict__ H0, __half* __restrict__ H1, __half* __restrict__ H2,
    float* __restrict__ Fout, const float* __restrict__ bias)
{
    extern __shared__ uint32_t smw[];
    uint32_t* Aw = smw;                   // [2][128*GW]
    uint32_t* Bw = smw + 2 * 128 * GW;
    const uint32_t abase = smem_u32(Aw);
    const uint32_t bbase = smem_u32(Bw);

    const __half* BT = WTbase + (size_t)blockIdx.z * ND * ND;

    const int tid = threadIdx.x;
    const int lane = tid & 31;
    const int wid = tid >> 5;
    const int g = lane >> 2, t = lane & 3;
    const int wm = wid & 3;
    const int wn = wid >> 2;
    const int m0 = blockIdx.y << 7;
    const int n0 = blockIdx.x << 7;

    const __half* Ab = A  + (size_t)m0 * ND;
    const __half* Bb = BT + (size_t)n0 * ND;

    float acc[2][8][4];
#pragma unroll
    for (int mt = 0; mt < 2; ++mt)
#pragma unroll
        for (int nt = 0; nt < 8; ++nt)
#pragma unroll
            for (int e = 0; e < 4; ++e) acc[mt][nt][e] = 0.f;

    auto issue = [&](int c, int buf) {
        const int k0h = c << 5;                      // halves
        const uint32_t bo = (uint32_t)buf * (128 * GW * 4);
#pragma unroll
        for (int u = 0; u < 2; ++u) {
            const int f = (u << 8) + tid;            // 0..511
            const int row = f >> 2, seg = f & 3;     // 4 x 16B per row
            const uint32_t d = bo + (uint32_t)(row * GW + (seg << 2)) * 4;
            cpa16(abase + d, Ab + (size_t)row * ND + k0h + (seg << 3));
            cpa16(bbase + d, Bb + (size_t)row * ND + k0h + (seg << 3));
        }
        CP_COMMIT();
    };

    issue(0, 0);

    const int rb0 = wm << 5, rb1 = rb0 + 16;
    for (int c = 0; c < 32; ++c) {
        CP_WAIT0();
        __syncthreads();
        if (c < 31) issue(c + 1, (c + 1) & 1);

        const uint32_t* Ac = Aw + (c & 1) * (128 * GW);
        const uint32_t* Bc = Bw + (c & 1) * (128 * GW);
#pragma unroll
        for (int ks = 0; ks < 2; ++ks) {
            const int wb = (ks << 3) + (t << 1);
            const uint2 a0l = *(const uint2*)&Ac[(rb0 + g    ) * GW + wb];
            const uint2 a0h = *(const uint2*)&Ac[(rb0 + g + 8) * GW + wb];
            const uint2 a1l = *(const uint2*)&Ac[(rb1 + g    ) * GW + wb];
            const uint2 a1h = *(const uint2*)&Ac[(rb1 + g + 8) * GW + wb];
            const uint32_t af0[4] = {a0l.x, a0h.x, a0l.y, a0h.y};
            const uint32_t af1[4] = {a1l.x, a1h.x, a1l.y, a1h.y};
#pragma unroll
            for (int nt = 0; nt < 8; ++nt) {
                const int cb = (wn << 6) + (nt << 3) + g;
                const uint2 b = *(const uint2*)&Bc[cb * GW + wb];
                mma16(acc[0][nt], af0, b.x, b.y);
                mma16(acc[1][nt], af1, b.x, b.y);
            }
        }
        // no trailing sync: next iter's wait+sync orders buffer reuse
    }

    // epilogue
#pragma unroll
    for (int mt = 0; mt < 2; ++mt) {
#pragma unroll
        for (int nt = 0; nt < 8; ++nt) {
            const int r0 = m0 + (wm << 5) + (mt << 4) + g;
            const int cc = n0 + (wn << 6) + (nt << 3) + (t << 1);
#pragma unroll
            for (int h = 0; h < 2; ++h) {
                const int m = r0 + (h << 3);
                const float v0 = acc[mt][nt][h * 2 + 0];
                const float v1 = acc[mt][nt][h * 2 + 1];
                if (MODE == 0) {
                    const int bb = m >> 11, tt = m & (NT - 1);
                    const int hh = cc >> 6, d = cc & 63;
                    const int bh = bb * NHH + hh;
                    if (blockIdx.z == 2) {
                        __half* vp = H2 + (((size_t)bh * NHD + d) * NT) + packh(tt);
                        vp[0]  = __float2half_rn(v0);
                        vp[NT] = __float2half_rn(v1);   // d+1 row
                    } else {
                        __half* qp = (blockIdx.z == 0) ? H0 : H1;
                        uint32_t* w = (uint32_t*)(qp + (((size_t)bh * NT + tt) << 6));
                        w[packh(d) >> 1] = h2pack(v0, v1);
                    }
                } else {
                    float* o = Fout + (size_t)m * ND + cc;
                    o[0] = v0 + bias[cc];
                    o[1] = v1 + bias[cc + 1];
                }
            }
        }
    }
}

// ---------------------------------------------------------------------------
// Causal flash attention, fp16 m16n8k16, 128 thr, q-tile 64, LPT order.
// K smem [t][packed d] / V smem [d][packed t], stride 40 words (conflict-free).
// PV A-fragment built from own S C-fragment (no shfl).
// ---------------------------------------------------------------------------
#define KW 40
__global__ void __launch_bounds__(128) attn_mma(
    const uint8_t* __restrict__ kpm, __half* __restrict__ Cctx)
{
    __shared__ uint32_t Kw[64 * KW];
    __shared__ uint32_t Vw[64 * KW];
    __shared__ float Msk[64];
    const uint32_t kbase = smem_u32(Kw);
    const uint32_t vbase = smem_u32(Vw);

    const int tid  = threadIdx.x;
    const int lane = tid & 31;
    const int wq   = tid >> 5;
    const int g = lane >> 2, t = lane & 3;
    const int qt = (int)(gridDim.x - 1) - (int)blockIdx.x;   // LPT
    const int bh = blockIdx.y;
    const int bb = bh >> 4, hh = bh & 15;
    const int q0 = qt << 6;

    const __half* Qh = g_Q + ((size_t)bh * NT << 6);
    const __half* Kh = g_K + ((size_t)bh * NT << 6);
    const __half* Vh = g_V + ((size_t)bh << 6) * NT;

    // Q fragments: 4 k16 steps over d=64, one LDG.64 pair per step
    uint32_t qf[4][4];
    const int qr0 = q0 + (wq << 4) + g;
#pragma unroll
    for (int ks = 0; ks < 4; ++ks) {
        const uint2 lo = *(const uint2*)(Qh + ((size_t)qr0 << 6) + (ks << 4) + (t << 2));
        const uint2 hi = *(const uint2*)(Qh + ((size_t)(qr0 + 8) << 6) + (ks << 4) + (t << 2));
        qf[ks][0] = lo.x; qf[ks][1] = hi.x;
        qf[ks][2] = lo.y; qf[ks][3] = hi.y;
    }

    const int r0 = qr0, r1 = qr0 + 8;
    float m0 = -1e30f, m1 = -1e30f, l0 = 0.f, l1 = 0.f;
    float oacc[8][4];
#pragma unroll
    for (int dt = 0; dt < 8; ++dt)
#pragma unroll
        for (int e = 0; e < 4; ++e) oacc[dt][e] = 0.f;

    for (int kt = 0; kt <= qt; ++kt) {
        const int k0 = kt << 6;
        __syncthreads();
#pragma unroll
        for (int u = 0; u < 4; ++u) {
            const int f = (u << 7) + tid;            // 0..511
            const int r = f >> 3, seg = f & 7;       // 8 x 16B per 128B row
            cpa16(kbase + (uint32_t)(r * KW + (seg << 2)) * 4,
                  Kh + ((size_t)(k0 + r) << 6) + (seg << 3));
            cpa16(vbase + (uint32_t)(r * KW + (seg << 2)) * 4,
                  Vh + (size_t)r * NT + k0 + (seg << 3));
        }
        CP_COMMIT();
        if (tid < 64)
            Msk[tid] = kpm[bb * NT + k0 + tid] ? -1e30f : 0.f;
        CP_WAIT0();
        __syncthreads();

        // ---- S = Q K^T ----
        float sacc[8][4];
#pragma unroll
        for (int nt = 0; nt < 8; ++nt)
#pragma unroll
            for (int e = 0; e < 4; ++e) sacc[nt][e] = 0.f;

#pragma unroll
        for (int ks = 0; ks < 4; ++ks) {
            const int wb = (ks << 3) + (t << 1);
#pragma unroll
            for (int nt = 0; nt < 8; ++nt) {
                const uint2 b = *(const uint2*)&Kw[((nt << 3) + g) * KW + wb];
                mma16(sacc[nt], qf[ks], b.x, b.y);
            }
        }

        // ---- scale + masks ----
        const bool diag = (kt == qt);
        float mx0 = -1e30f, mx1 = -1e30f;
#pragma unroll
        for (int nt = 0; nt < 8; ++nt) {
            const int cl = (nt << 3) + (t << 1);
            const int kv0 = k0 + cl, kv1 = kv0 + 1;
            const float pm0 = Msk[cl], pm1 = Msk[cl + 1];
            float s0 = sacc[nt][0] * 0.125f + pm0;
            float s1 = sacc[nt][1] * 0.125f + pm1;
            float s2 = sacc[nt][2] * 0.125f + pm0;
            float s3 = sacc[nt][3] * 0.125f + pm1;
            if (diag) {
                if (kv0 > r0) s0 = -1e30f;
                if (kv1 > r0) s1 = -1e30f;
                if (kv0 > r1) s2 = -1e30f;
                if (kv1 > r1) s3 = -1e30f;
            }
            sacc[nt][0] = s0; sacc[nt][1] = s1;
            sacc[nt][2] = s2; sacc[nt][3] = s3;
            mx0 = fmaxf(mx0, fmaxf(s0, s1));
            mx1 = fmaxf(mx1, fmaxf(s2, s3));
        }
        mx0 = fmaxf(mx0, __shfl_xor_sync(0xffffffffu, mx0, 1));
        mx0 = fmaxf(mx0, __shfl_xor_sync(0xffffffffu, mx0, 2));
        mx1 = fmaxf(mx1, __shfl_xor_sync(0xffffffffu, mx1, 1));
        mx1 = fmaxf(mx1, __shfl_xor_sync(0xffffffffu, mx1, 2));

        const float nm0 = fmaxf(m0, mx0), nm1 = fmaxf(m1, mx1);
        const float cr0 = __expf(m0 - nm0), cr1 = __expf(m1 - nm1);
        m0 = nm0; m1 = nm1;

        float sum0 = 0.f, sum1 = 0.f;
#pragma unroll
        for (int nt = 0; nt < 8; ++nt) {
            const float p0 = __expf(sacc[nt][0] - nm0);
            const float p1 = __expf(sacc[nt][1] - nm0);
            const float p2 = __expf(sacc[nt][2] - nm1);
            const float p3 = __expf(sacc[nt][3] - nm1);
            sacc[nt][0] = p0; sacc[nt][1] = p1;
            sacc[nt][2] = p2; sacc[nt][3] = p3;
            sum0 += p0 + p1; sum1 += p2 + p3;
        }
        sum0 += __shfl_xor_sync(0xffffffffu, sum0, 1);
        sum0 += __shfl_xor_sync(0xffffffffu, sum0, 2);
        sum1 += __shfl_xor_sync(0xffffffffu, sum1, 1);
        sum1 += __shfl_xor_sync(0xffffffffu, sum1, 2);
        l0 = l0 * cr0 + sum0;
        l1 = l1 * cr1 + sum1;
#pragma unroll
        for (int dt = 0; dt < 8; ++dt) {
            oacc[dt][0] *= cr0; oacc[dt][1] *= cr0;
            oacc[dt][2] *= cr1; oacc[dt][3] *= cr1;
        }

        // ---- O += P V ----  (A-frag = own C-frag pairs, no shfl)
#pragma unroll
        for (int j = 0; j < 4; ++j) {
            const uint32_t a[4] = {
                h2pack(sacc[2 * j][0],     sacc[2 * j][1]),
                h2pack(sacc[2 * j][2],     sacc[2 * j][3]),
                h2pack(sacc[2 * j + 1][0], sacc[2 * j + 1][1]),
                h2pack(sacc[2 * j + 1][2], sacc[2 * j + 1][3])
            };
            const int wb = (j << 3) + (t << 1);
#pragma unroll
            for (int dt = 0; dt < 8; ++dt) {
                const uint2 b = *(const uint2*)&Vw[((dt << 3) + g) * KW + wb];
                mma16(oacc[dt], a, b.x, b.y);
            }
        }
    }

    // ---- normalize + write ctx [m][packed ND-col] as half2 words ----
    const float i0 = 1.f / l0, i1 = 1.f / l1;
    const int mrow0 = (bb << 11) + q0 + (wq << 4) + g;
    uint32_t* Cw = (uint32_t*)Cctx;
#pragma unroll
    for (int dt = 0; dt < 8; ++dt) {
        const int dc = (hh << 6) + (dt << 3) + (t << 1);
        const int wslot = packh(dc) >> 1;
        Cw[(size_t)mrow0 * (ND / 2) + wslot] =
            h2pack(oacc[dt][0] * i0, oacc[dt][1] * i0);
        Cw[(size_t)(mrow0 + 8) * (ND / 2) + wslot] =
            h2pack(oacc[dt][2] * i1, oacc[dt][3] * i1);
    }
}

// ---------------------------------------------------------------------------
extern "C" void kernel_launch(void* const* d_in, const int* in_sizes, int n_in,
                              void* d_out, int out_size)
{
    (void)in_sizes; (void)n_in; (void)out_size;
    const float*   x   = (const float*)d_in[0];
    const float*   Wq  = (const float*)d_in[1];
    const float*   Wk  = (const float*)d_in[2];
    const float*   Wv  = (const float*)d_in[3];
    const float*   Wo  = (const float*)d_in[4];
    const float*   bo  = (const float*)d_in[5];
    const uint8_t* kpm = (const uint8_t*)d_in[6];
    float* out = (float*)d_out;

    __half *Xp, *Qp, *Kp, *Vp, *Cp, *WTp;
    cudaGetSymbolAddress((void**)&Xp, g_X);
    cudaGetSymbolAddress((void**)&Qp, g_Q);
    cudaGetSymbolAddress((void**)&Kp, g_K);
    cudaGetSymbolAddress((void**)&Vp, g_V);
    cudaGetSymbolAddress((void**)&Cp, g_C);
    cudaGetSymbolAddress((void**)&WTp, g_WT);

    round_x<<<(NM * ND) / (256 * 16), 256>>>(x, Xp);
    transpose_w4<<<dim3(32, 32, 4), dim3(32, 8)>>>(Wq, Wk, Wv, Wo, WTp);

    const int gsmem = 2 * 2 * 128 * GW * (int)sizeof(uint32_t);  // 49152
    cudaFuncSetAttribute(gemm_mma<0>, cudaFuncAttributeMaxDynamicSharedMemorySize, gsmem);
    cudaFuncSetAttribute(gemm_mma<1>, cudaFuncAttributeMaxDynamicSharedMemorySize, gsmem);

    // fused Q/K/V projections: grid.z selects weight + destination/layout
    gemm_mma<0><<<dim3(ND / 128, NM / 128, 3), 256, gsmem>>>(
        Xp, WTp, Qp, Kp, Vp, nullptr, nullptr);

    attn_mma<<<dim3(NT / 64, NB * NHH), 128>>>(kpm, Cp);

    gemm_mma<1><<<dim3(ND / 128, NM / 128, 1), 256, gsmem>>>(
        Cp, WTp + 3 * (size_t)ND * ND, nullptr, nullptr, nullptr, out, bo);
}

// round 14
// speedup vs baseline: 2.9670x; 1.0531x over previous
#include <cuda_runtime.h>
#include <cuda_fp16.h>
#include <cstdint>

#define NB   2
#define NT   2048
#define ND   1024
#define NHH  16
#define NHD  64
#define NM   (NB * NT)   // 4096 rows

// Scratch (device globals: allocation is forbidden). All fp16, pair-packed.
__device__ __half g_X[NM * ND];               // input, k word-packed
__device__ __half g_Q[NB * NHH * NT * NHD];   // [b,h,t,packh(d)]
__device__ __half g_K[NB * NHH * NT * NHD];   // [b,h,t,packh(d)]
__device__ __half g_V[NB * NHH * NT * NHD];   // [b,h,d,packh(t)] (transposed)
__device__ __half g_C[NM * ND];               // ctx, k word-packed
__device__ __half g_WT[4 * ND * ND];          // W^T [n][k] word-packed

// ---------------------------------------------------------------------------
// Helpers
// ---------------------------------------------------------------------------
__device__ __forceinline__ uint32_t smem_u32(const void* p) {
    uint32_t a;
    asm("{ .reg .u64 t; cvta.to.shared.u64 t, %1; cvt.u32.u64 %0, t; }"
        : "=r"(a) : "l"(p));
    return a;
}
__device__ __forceinline__ uint32_t h2pack(float lo, float hi) {
    __half2 h = __floats2half2_rn(lo, hi);
    return *reinterpret_cast<uint32_t*>(&h);
}
__device__ __forceinline__ float ex2(float x) {
    float r; asm("ex2.approx.f32 %0, %1;" : "=f"(r) : "f"(x)); return r;
}
__device__ __forceinline__ void cpa16(uint32_t dst, const void* src) {
    asm volatile("cp.async.cg.shared.global [%0], [%1], 16;" :: "r"(dst), "l"(src));
}
#define CP_COMMIT() asm volatile("cp.async.commit_group;" ::: "memory")
#define CP_WAIT0()  asm volatile("cp.async.wait_group 0;" ::: "memory")

// half-index pack within groups of 16 halves (8 words): word j -> slot
// ((j&3)<<1)|((j>>2)&1). Packed k order: 0,1,8,9,2,3,10,11,4,5,12,13,6,7,14,15
// => LDS.64 at word offset 2t yields halves (2t,2t+1),(2t+8,2t+9) = the
// m16n8k16 fragment pairs.
__device__ __forceinline__ int packh(int k) {
    const int j = (k >> 1) & 7;
    return (k & ~15) | (((((j & 3) << 1) | ((j >> 2) & 1))) << 1) | (k & 1);
}

// mma.sync m16n8k16 row.col fp16 -> f32: d += a * b
__device__ __forceinline__ void mma16(float* d, const uint32_t* a,
                                      uint32_t b0, uint32_t b1)
{
    asm volatile(
        "mma.sync.aligned.m16n8k16.row.col.f32.f16.f16.f32 "
        "{%0,%1,%2,%3}, {%4,%5,%6,%7}, {%8,%9}, {%0,%1,%2,%3};"
        : "+f"(d[0]), "+f"(d[1]), "+f"(d[2]), "+f"(d[3])
        : "r"(a[0]), "r"(a[1]), "r"(a[2]), "r"(a[3]), "r"(b0), "r"(b1));
}

// ---------------------------------------------------------------------------
// x (f32) -> g_X (f16, word-packed). One 16-half group per thread.
// ---------------------------------------------------------------------------
__global__ void round_x(const float* __restrict__ src, __half* __restrict__ dst)
{
    const int gid = blockIdx.x * 256 + threadIdx.x;
    const int i = gid << 4;
    const float4 f0 = *(const float4*)(src + i);
    const float4 f1 = *(const float4*)(src + i + 4);
    const float4 f2 = *(const float4*)(src + i + 8);
    const float4 f3 = *(const float4*)(src + i + 12);
    uint4 w0, w1;
    w0.x = h2pack(f0.x, f0.y); w0.y = h2pack(f2.x, f2.y);
    w0.z = h2pack(f0.z, f0.w); w0.w = h2pack(f2.z, f2.w);
    w1.x = h2pack(f1.x, f1.y); w1.y = h2pack(f3.x, f3.y);
    w1.z = h2pack(f1.z, f1.w); w1.w = h2pack(f3.z, f3.w);
    ((uint4*)dst)[gid * 2]     = w0;
    ((uint4*)dst)[gid * 2 + 1] = w1;
}

// ---------------------------------------------------------------------------
// Weight transpose + f16 + pack: WT[z][n][packh(k)] = f16(W_z[k][n])
// ---------------------------------------------------------------------------
__global__ void transpose_w4(const float* __restrict__ W0,
                             const float* __restrict__ W1,
                             const float* __restrict__ W2,
                             const float* __restrict__ W3,
                             __half* __restrict__ WT)
{
    const float* W = (blockIdx.z == 0) ? W0 : (blockIdx.z == 1) ? W1
                   : (blockIdx.z == 2) ? W2 : W3;
    __half* dst = WT + (size_t)blockIdx.z * ND * ND;

    __shared__ float t[32][33];
    const int x = (blockIdx.x << 5) + threadIdx.x;
    const int y0 = (blockIdx.y << 5) + threadIdx.y;
#pragma unroll
    for (int i = 0; i < 32; i += 8)
        t[threadIdx.y + i][threadIdx.x] = W[(size_t)(y0 + i) * ND + x];
    __syncthreads();
    const int x2 = (blockIdx.y << 5) + threadIdx.x;   // k
    const int y2 = (blockIdx.x << 5) + threadIdx.y;   // n
    const int pk = packh(x2);
#pragma unroll
    for (int i = 0; i < 32; i += 8)
        dst[(size_t)(y2 + i) * ND + pk] = __float2half_rn(t[threadIdx.x][threadIdx.y + i]);
}

// ---------------------------------------------------------------------------
// fp16 m16n8k16 GEMM, cp.async 2-stage, BK=64 halves (4 k16 steps, 16 chunks).
// 128x128 tile, 8 warps (4m x 2n), warp tile 32x64.
// MODE 0: grid.z 0/1 -> Q/K [b,h,t,packh(d)]; z=2 -> V [b,h,d,packh(t)].
// MODE 1: f32 row-major + bias (final output).
// ---------------------------------------------------------------------------
#define GW 40     // smem words per row (32 data + 8 pad) - conflict-free
template <int MODE>
__global__ void __launch_bounds__(256) gemm_mma(
    const __half* __restrict__ A, const __half* __restrict__ WTbase,
    __half* __restrict__ H0, __half* __restrict__ H1, __half* __restrict__ H2,
    float* __restrict__ Fout, const float* __restrict__ bias)
{
    extern __shared__ uint32_t smw[];
    uint32_t* Aw = smw;                   // [2][128*GW]
    uint32_t* Bw = smw + 2 * 128 * GW;
    const uint32_t abase = smem_u32(Aw);
    const uint32_t bbase = smem_u32(Bw);

    const __half* BT = WTbase + (size_t)blockIdx.z * ND * ND;

    const int tid = threadIdx.x;
    const int lane = tid & 31;
    const int wid = tid >> 5;
    const int g = lane >> 2, t = lane & 3;
    const int wm = wid & 3;
    const int wn = wid >> 2;
    const int m0 = blockIdx.y << 7;
    const int n0 = blockIdx.x << 7;

    const __half* Ab = A  + (size_t)m0 * ND;
    const __half* Bb = BT + (size_t)n0 * ND;

    float acc[2][8][4];
#pragma unroll
    for (int mt = 0; mt < 2; ++mt)
#pragma unroll
        for (int nt = 0; nt < 8; ++nt)
#pragma unroll
            for (int e = 0; e < 4; ++e) acc[mt][nt][e] = 0.f;

    auto issue = [&](int c, int buf) {
        const int k0h = c << 6;                      // halves
        const uint32_t bo = (uint32_t)buf * (128 * GW * 4);
#pragma unroll
        for (int u = 0; u < 4; ++u) {
            const int f = (u << 8) + tid;            // 0..1023
            const int row = f >> 3, seg = f & 7;     // 8 x 16B per row
            const uint32_t d = bo + (uint32_t)(row * GW + (seg << 2)) * 4;
            cpa16(abase + d, Ab + (size_t)row * ND + k0h + (seg << 3));
            cpa16(bbase + d, Bb + (size_t)row * ND + k0h + (seg << 3));
        }
        CP_COMMIT();
    };

    issue(0, 0);

    const int rb0 = wm << 5, rb1 = rb0 + 16;
    for (int c = 0; c < 16; ++c) {
        CP_WAIT0();
        __syncthreads();
        if (c < 15) issue(c + 1, (c + 1) & 1);

        const uint32_t* Ac = Aw + (c & 1) * (128 * GW);
        const uint32_t* Bc = Bw + (c & 1) * (128 * GW);
#pragma unroll
        for (int ks = 0; ks < 4; ++ks) {
            const int wb = (ks << 3) + (t << 1);
            const uint2 a0l = *(const uint2*)&Ac[(rb0 + g    ) * GW + wb];
            const uint2 a0h = *(const uint2*)&Ac[(rb0 + g + 8) * GW + wb];
            const uint2 a1l = *(const uint2*)&Ac[(rb1 + g    ) * GW + wb];
            const uint2 a1h = *(const uint2*)&Ac[(rb1 + g + 8) * GW + wb];
            const uint32_t af0[4] = {a0l.x, a0h.x, a0l.y, a0h.y};
            const uint32_t af1[4] = {a1l.x, a1h.x, a1l.y, a1h.y};
#pragma unroll
            for (int nt = 0; nt < 8; ++nt) {
                const int cb = (wn << 6) + (nt << 3) + g;
                const uint2 b = *(const uint2*)&Bc[cb * GW + wb];
                mma16(acc[0][nt], af0, b.x, b.y);
                mma16(acc[1][nt], af1, b.x, b.y);
            }
        }
        // no trailing sync: next iter's wait+sync orders buffer reuse
    }

    // epilogue
#pragma unroll
    for (int mt = 0; mt < 2; ++mt) {
#pragma unroll
        for (int nt = 0; nt < 8; ++nt) {
            const int r0 = m0 + (wm << 5) + (mt << 4) + g;
            const int cc = n0 + (wn << 6) + (nt << 3) + (t << 1);
#pragma unroll
            for (int h = 0; h < 2; ++h) {
                const int m = r0 + (h << 3);
                const float v0 = acc[mt][nt][h * 2 + 0];
                const float v1 = acc[mt][nt][h * 2 + 1];
                if (MODE == 0) {
                    const int bb = m >> 11, tt = m & (NT - 1);
                    const int hh = cc >> 6, d = cc & 63;
                    const int bh = bb * NHH + hh;
                    if (blockIdx.z == 2) {
                        __half* vp = H2 + (((size_t)bh * NHD + d) * NT) + packh(tt);
                        vp[0]  = __float2half_rn(v0);
                        vp[NT] = __float2half_rn(v1);   // d+1 row
                    } else {
                        __half* qp = (blockIdx.z == 0) ? H0 : H1;
                        uint32_t* w = (uint32_t*)(qp + (((size_t)bh * NT + tt) << 6));
                        w[packh(d) >> 1] = h2pack(v0, v1);
                    }
                } else {
                    float* o = Fout + (size_t)m * ND + cc;
                    o[0] = v0 + bias[cc];
                    o[1] = v1 + bias[cc + 1];
                }
            }
        }
    }
}

// ---------------------------------------------------------------------------
// Causal flash attention, fp16 m16n8k16, 128 thr, q-tile 64, LPT order.
// Softmax in exp2 domain: s = S*(0.125*log2e) + mask; p = ex2(s - m).
// K smem [t][packed d] / V smem [d][packed t], stride 40 words.
// PV A-fragment built from own S C-fragment (no shfl).
// ---------------------------------------------------------------------------
#define KW 40
#define SCL2 0.180336879f    // 0.125 * log2(e)
__global__ void __launch_bounds__(128) attn_mma(
    const uint8_t* __restrict__ kpm, __half* __restrict__ Cctx)
{
    __shared__ uint32_t Kw[64 * KW];
    __shared__ uint32_t Vw[64 * KW];
    __shared__ float Msk[64];
    const uint32_t kbase = smem_u32(Kw);
    const uint32_t vbase = smem_u32(Vw);

    const int tid  = threadIdx.x;
    const int lane = tid & 31;
    const int wq   = tid >> 5;
    const int g = lane >> 2, t = lane & 3;
    const int qt = (int)(gridDim.x - 1) - (int)blockIdx.x;   // LPT
    const int bh = blockIdx.y;
    const int bb = bh >> 4, hh = bh & 15;
    const int q0 = qt << 6;

    const __half* Qh = g_Q + ((size_t)bh * NT << 6);
    const __half* Kh = g_K + ((size_t)bh * NT << 6);
    const __half* Vh = g_V + ((size_t)bh << 6) * NT;

    // Q fragments: 4 k16 steps over d=64
    uint32_t qf[4][4];
    const int qr0 = q0 + (wq << 4) + g;
#pragma unroll
    for (int ks = 0; ks < 4; ++ks) {
        const uint2 lo = *(const uint2*)(Qh + ((size_t)qr0 << 6) + (ks << 4) + (t << 2));
        const uint2 hi = *(const uint2*)(Qh + ((size_t)(qr0 + 8) << 6) + (ks << 4) + (t << 2));
        qf[ks][0] = lo.x; qf[ks][1] = hi.x;
        qf[ks][2] = lo.y; qf[ks][3] = hi.y;
    }

    const int r0 = qr0, r1 = qr0 + 8;
    float m0 = -1e30f, m1 = -1e30f, l0 = 0.f, l1 = 0.f;
    float oacc[8][4];
#pragma unroll
    for (int dt = 0; dt < 8; ++dt)
#pragma unroll
        for (int e = 0; e < 4; ++e) oacc[dt][e] = 0.f;

    for (int kt = 0; kt <= qt; ++kt) {
        const int k0 = kt << 6;
        __syncthreads();
#pragma unroll
        for (int u = 0; u < 4; ++u) {
            const int f = (u << 7) + tid;            // 0..511
            const int r = f >> 3, seg = f & 7;       // 8 x 16B per 128B row
            cpa16(kbase + (uint32_t)(r * KW + (seg << 2)) * 4,
                  Kh + ((size_t)(k0 + r) << 6) + (seg << 3));
            cpa16(vbase + (uint32_t)(r * KW + (seg << 2)) * 4,
                  Vh + (size_t)r * NT + k0 + (seg << 3));
        }
        CP_COMMIT();
        if (tid < 64)
            Msk[tid] = kpm[bb * NT + k0 + tid] ? -1e30f : 0.f;
        CP_WAIT0();
        __syncthreads();

        // ---- S = Q K^T ----
        float sacc[8][4];
#pragma unroll
        for (int nt = 0; nt < 8; ++nt)
#pragma unroll
            for (int e = 0; e < 4; ++e) sacc[nt][e] = 0.f;

#pragma unroll
        for (int ks = 0; ks < 4; ++ks) {
            const int wb = (ks << 3) + (t << 1);
#pragma unroll
            for (int nt = 0; nt < 8; ++nt) {
                const uint2 b = *(const uint2*)&Kw[((nt << 3) + g) * KW + wb];
                mma16(sacc[nt], qf[ks], b.x, b.y);
            }
        }

        // ---- scale (log2 domain) + masks ----
        const bool diag = (kt == qt);
        float mx0 = -1e30f, mx1 = -1e30f;
#pragma unroll
        for (int nt = 0; nt < 8; ++nt) {
            const int cl = (nt << 3) + (t << 1);
            const int kv0 = k0 + cl, kv1 = kv0 + 1;
            const float pm0 = Msk[cl], pm1 = Msk[cl + 1];
            float s0 = sacc[nt][0] * SCL2 + pm0;
            float s1 = sacc[nt][1] * SCL2 + pm1;
            float s2 = sacc[nt][2] * SCL2 + pm0;
            float s3 = sacc[nt][3] * SCL2 + pm1;
            if (diag) {
                if (kv0 > r0) s0 = -1e30f;
                if (kv1 > r0) s1 = -1e30f;
                if (kv0 > r1) s2 = -1e30f;
                if (kv1 > r1) s3 = -1e30f;
            }
            sacc[nt][0] = s0; sacc[nt][1] = s1;
            sacc[nt][2] = s2; sacc[nt][3] = s3;
            mx0 = fmaxf(mx0, fmaxf(s0, s1));
            mx1 = fmaxf(mx1, fmaxf(s2, s3));
        }
        mx0 = fmaxf(mx0, __shfl_xor_sync(0xffffffffu, mx0, 1));
        mx0 = fmaxf(mx0, __shfl_xor_sync(0xffffffffu, mx0, 2));
        mx1 = fmaxf(mx1, __shfl_xor_sync(0xffffffffu, mx1, 1));
        mx1 = fmaxf(mx1, __shfl_xor_sync(0xffffffffu, mx1, 2));

        const float nm0 = fmaxf(m0, mx0), nm1 = fmaxf(m1, mx1);
        const float cr0 = ex2(m0 - nm0), cr1 = ex2(m1 - nm1);
        m0 = nm0; m1 = nm1;

        float sum0 = 0.f, sum1 = 0.f;
#pragma unroll
        for (int nt = 0; nt < 8; ++nt) {
            const float p0 = ex2(sacc[nt][0] - nm0);
            const float p1 = ex2(sacc[nt][1] - nm0);
            const float p2 = ex2(sacc[nt][2] - nm1);
            const float p3 = ex2(sacc[nt][3] - nm1);
            sacc[nt][0] = p0; sacc[nt][1] = p1;
            sacc[nt][2] = p2; sacc[nt][3] = p3;
            sum0 += p0 + p1; sum1 += p2 + p3;
        }
        sum0 += __shfl_xor_sync(0xffffffffu, sum0, 1);
        sum0 += __shfl_xor_sync(0xffffffffu, sum0, 2);
        sum1 += __shfl_xor_sync(0xffffffffu, sum1, 1);
        sum1 += __shfl_xor_sync(0xffffffffu, sum1, 2);
        l0 = l0 * cr0 + sum0;
        l1 = l1 * cr1 + sum1;
#pragma unroll
        for (int dt = 0; dt < 8; ++dt) {
            oacc[dt][0] *= cr0; oacc[dt][1] *= cr0;
            oacc[dt][2] *= cr1; oacc[dt][3] *= cr1;
        }

        // ---- O += P V ----  (A-frag = own C-frag pairs, no shfl)
#pragma unroll
        for (int j = 0; j < 4; ++j) {
            const uint32_t a[4] = {
                h2pack(sacc[2 * j][0],     sacc[2 * j][1]),
                h2pack(sacc[2 * j][2],     sacc[2 * j][3]),
                h2pack(sacc[2 * j + 1][0], sacc[2 * j + 1][1]),
                h2pack(sacc[2 * j + 1][2], sacc[2 * j + 1][3])
            };
            const int wb = (j << 3) + (t << 1);
#pragma unroll
            for (int dt = 0; dt < 8; ++dt) {
                const uint2 b = *(const uint2*)&Vw[((dt << 3) + g) * KW + wb];
                mma16(oacc[dt], a, b.x, b.y);
            }
        }
    }

    // ---- normalize + write ctx [m][packed ND-col] as half2 words ----
    const float i0 = 1.f / l0, i1 = 1.f / l1;
    const int mrow0 = (bb << 11) + q0 + (wq << 4) + g;
    uint32_t* Cw = (uint32_t*)Cctx;
#pragma unroll
    for (int dt = 0; dt < 8; ++dt) {
        const int dc = (hh << 6) + (dt << 3) + (t << 1);
        const int wslot = packh(dc) >> 1;
        Cw[(size_t)mrow0 * (ND / 2) + wslot] =
            h2pack(oacc[dt][0] * i0, oacc[dt][1] * i0);
        Cw[(size_t)(mrow0 + 8) * (ND / 2) + wslot] =
            h2pack(oacc[dt][2] * i1, oacc[dt][3] * i1);
    }
}

// ---------------------------------------------------------------------------
extern "C" void kernel_launch(void* const* d_in, const int* in_sizes, int n_in,
                              void* d_out, int out_size)
{
    (void)in_sizes; (void)n_in; (void)out_size;
    const float*   x   = (const float*)d_in[0];
    const float*   Wq  = (const float*)d_in[1];
    const float*   Wk  = (const float*)d_in[2];
    const float*   Wv  = (const float*)d_in[3];
    const float*   Wo  = (const float*)d_in[4];
    const float*   bo  = (const float*)d_in[5];
    const uint8_t* kpm = (const uint8_t*)d_in[6];
    float* out = (float*)d_out;

    __half *Xp, *Qp, *Kp, *Vp, *Cp, *WTp;
    cudaGetSymbolAddress((void**)&Xp, g_X);
    cudaGetSymbolAddress((void**)&Qp, g_Q);
    cudaGetSymbolAddress((void**)&Kp, g_K);
    cudaGetSymbolAddress((void**)&Vp, g_V);
    cudaGetSymbolAddress((void**)&Cp, g_C);
    cudaGetSymbolAddress((void**)&WTp, g_WT);

    round_x<<<(NM * ND) / (256 * 16), 256>>>(x, Xp);
    transpose_w4<<<dim3(32, 32, 4), dim3(32, 8)>>>(Wq, Wk, Wv, Wo, WTp);

    const int gsmem = 2 * 2 * 128 * GW * (int)sizeof(uint32_t);  // 81920
    cudaFuncSetAttribute(gemm_mma<0>, cudaFuncAttributeMaxDynamicSharedMemorySize, gsmem);
    cudaFuncSetAttribute(gemm_mma<1>, cudaFuncAttributeMaxDynamicSharedMemorySize, gsmem);

    // fused Q/K/V projections: grid.z selects weight + destination/layout
    gemm_mma<0><<<dim3(ND / 128, NM / 128, 3), 256, gsmem>>>(
        Xp, WTp, Qp, Kp, Vp, nullptr, nullptr);

    attn_mma<<<dim3(NT / 64, NB * NHH), 128>>>(kpm, Cp);

    gemm_mma<1><<<dim3(ND / 128, NM / 128, 1), 256, gsmem>>>(
        Cp, WTp + 3 * (size_t)ND * ND, nullptr, nullptr, nullptr, out, bo);
}